// round 13
// baseline (speedup 1.0000x reference)
#include <cuda_runtime.h>
#include <mma.h>
#include <cstdint>

using namespace nvcuda;

// ---------------------------------------------------------------------------
// VisionSdpaAttention — v10: tcgen05 GEMMs (bias-fused) + widened mma.sync
// attention (256 thr / 256-row tiles, online softmax on raw EX2)
//   L=1024, B=8, C=1024, H=16, D=64
// ---------------------------------------------------------------------------

#if defined(__CUDA_ARCH_FEAT_SM103_ALL) || defined(__CUDA_ARCH_FEAT_SM100_ALL)
#define HAS_TCGEN05 1
#else
#define HAS_TCGEN05 0
#endif

__device__ float g_hs[8388608];               // tf32-rounded hidden_states
__device__ float g_wqkv[3145728];             // tf32-rounded Wqkv
__device__ float g_wo[1048576];               // tf32-rounded Wo
__device__ float g_qkv[25165824];             // (L*B, 3C)
__device__ float g_q[8388608];                // (B,H,L,D) tf32, scaled 0.125*log2(e)
__device__ float g_k[8388608];
__device__ float g_v[8388608];
__device__ float g_attn[8388608];             // (L*B, C) tf32-rounded
__device__ unsigned long long g_maskbits[131072];  // [B][16 kt][1024 rows]
__device__ int g_mask_mode;
__device__ int g_use_tc;

__device__ __forceinline__ float to_tf32(float x) {
    unsigned int u;
    asm("cvt.rna.tf32.f32 %0, %1;" : "=r"(u) : "f"(x));
    return __uint_as_float(u);
}
__device__ __forceinline__ float ex2_fast(float x) {
    float r;
    asm("ex2.approx.ftz.f32 %0, %1;" : "=f"(r) : "f"(x));
    return r;
}
__device__ __forceinline__ void cp_async16(void* sptr, const void* gptr) {
    unsigned s = (unsigned)__cvta_generic_to_shared(sptr);
    asm volatile("cp.async.cg.shared.global [%0], [%1], 16;" :: "r"(s), "l"(gptr));
}
__device__ __forceinline__ void cp_async16s(uint32_t saddr, const void* gptr) {
    asm volatile("cp.async.cg.shared.global [%0], [%1], 16;" :: "r"(saddr), "l"(gptr));
}
__device__ __forceinline__ void cp_commit() {
    asm volatile("cp.async.commit_group;");
}
__device__ __forceinline__ void mma8(float* c, const unsigned* a, unsigned b0, unsigned b1) {
    asm volatile(
        "mma.sync.aligned.m16n8k8.row.col.f32.tf32.tf32.f32 "
        "{%0,%1,%2,%3},{%4,%5,%6,%7},{%8,%9},{%0,%1,%2,%3};"
        : "+f"(c[0]), "+f"(c[1]), "+f"(c[2]), "+f"(c[3])
        : "r"(a[0]), "r"(a[1]), "r"(a[2]), "r"(a[3]), "r"(b0), "r"(b1));
}
__device__ __forceinline__ uint32_t smem_u32(const void* p) {
    return (uint32_t)__cvta_generic_to_shared(p);
}

__global__ void probe_tc_kernel() { if (threadIdx.x == 0) g_use_tc = HAS_TCGEN05; }

// ---------------------------------------------------------------------------
// tf32 rounding copy
// ---------------------------------------------------------------------------
__global__ __launch_bounds__(256) void tf32_round_kernel(
    float* __restrict__ dst, const float* __restrict__ src, int n4)
{
    int i = blockIdx.x * 256 + threadIdx.x;
    if (i >= n4) return;
    float4 v = *((const float4*)src + i);
    v.x = to_tf32(v.x); v.y = to_tf32(v.y);
    v.z = to_tf32(v.z); v.w = to_tf32(v.w);
    *((float4*)dst + i) = v;
}

// ---------------------------------------------------------------------------
// Mask detection + bitpack -> layout [b][kt][row]
// ---------------------------------------------------------------------------
__global__ void detect_mask_mode_kernel(const unsigned char* __restrict__ m)
{
    __shared__ int s1, s23;
    const int tid = threadIdx.x;
    if (tid == 0) { s1 = 0; s23 = 0; }
    __syncthreads();
    bool o1 = false, o23 = false;
    for (int i = tid * 4; i < 16384; i += 1024) {
        if (m[i + 1] != 0) o1 = true;
        if (m[i + 2] != 0 || m[i + 3] != 0) o23 = true;
    }
    if (o1) atomicOr(&s1, 1);
    if (o23) atomicOr(&s23, 1);
    __syncthreads();
    if (tid == 0) g_mask_mode = s1 ? 0 : (s23 ? 2 : 1);
}

__global__ __launch_bounds__(256) void convert_mask_bits_kernel(const void* __restrict__ mp)
{
    const int idx = blockIdx.x * 256 + threadIdx.x;   // input word: (b*1024+row)*16+kt
    const int mode = g_mask_mode;
    unsigned long long bits = 0ULL;
    const size_t base = (size_t)idx * 64;
    if (mode == 0) {
        const uint4* p = (const uint4*)((const unsigned char*)mp + base);
#pragma unroll
        for (int wrd = 0; wrd < 4; wrd++) {
            uint4 v = p[wrd];
            unsigned ws[4] = {v.x, v.y, v.z, v.w};
#pragma unroll
            for (int q = 0; q < 4; q++)
#pragma unroll
                for (int by = 0; by < 4; by++)
                    if ((ws[q] >> (by * 8)) & 0xffu)
                        bits |= 1ULL << (wrd * 16 + q * 4 + by);
        }
    } else if (mode == 1) {
        const int* p = (const int*)mp + base;
#pragma unroll 8
        for (int j = 0; j < 64; j++)
            if (p[j] != 0) bits |= 1ULL << j;
    } else {
        const float* p = (const float*)mp + base;
#pragma unroll 8
        for (int j = 0; j < 64; j++)
            if (p[j] != 0.0f) bits |= 1ULL << j;
    }
    const int b = idx >> 14;
    const int row = (idx >> 4) & 1023;
    const int kt = idx & 15;
    g_maskbits[((size_t)b * 16 + kt) * 1024 + row] = bits;
}

// ===========================================================================
// tcgen05 helpers + GEMM (verified in R9; bias fused in epilogue)
// ===========================================================================
#if HAS_TCGEN05
__device__ __forceinline__ uint32_t elect_one_pred() {
    uint32_t pred;
    asm volatile(
        "{\n\t.reg .pred p;\n\telect.sync _|p, 0xFFFFFFFF;\n\t"
        "selp.b32 %0, 1, 0, p;\n\t}" : "=r"(pred));
    return pred;
}
static __device__ __forceinline__ uint64_t make_desc_sw128(uint32_t addr) {
    return ((uint64_t)2u << 61) | ((uint64_t)1u << 46) | ((uint64_t)64u << 32)
         | ((uint64_t)1u << 16) | ((uint64_t)(addr >> 4) & 0x3FFFu);
}
__device__ __forceinline__ void tcgen05_mma_tf32_ss(
    uint32_t d_tmem, uint64_t a_desc, uint64_t b_desc, uint32_t idesc, bool enable_d)
{
    uint32_t en = enable_d ? 1u : 0u;
    asm volatile(
        "{\n\t.reg .pred p;\n\t"
        "setp.ne.u32 p, %5, 0;\n\t"
        "tcgen05.mma.cta_group::1.kind::tf32 [%0], %1, %2, %3, {%4, %4, %4, %4}, p;\n\t"
        "}"
        :: "r"(d_tmem), "l"(a_desc), "l"(b_desc), "r"(idesc), "r"(0u), "r"(en)
        : "memory");
}
#define TC_LD_X32(r, addr) \
    asm volatile( \
        "tcgen05.ld.sync.aligned.32x32b.x32.b32 " \
        "{%0, %1, %2, %3, %4, %5, %6, %7, " \
        " %8, %9, %10, %11, %12, %13, %14, %15, " \
        " %16, %17, %18, %19, %20, %21, %22, %23, " \
        " %24, %25, %26, %27, %28, %29, %30, %31}, [%32];" \
        : "=r"((r)[0]),  "=r"((r)[1]),  "=r"((r)[2]),  "=r"((r)[3]), \
          "=r"((r)[4]),  "=r"((r)[5]),  "=r"((r)[6]),  "=r"((r)[7]), \
          "=r"((r)[8]),  "=r"((r)[9]),  "=r"((r)[10]), "=r"((r)[11]), \
          "=r"((r)[12]), "=r"((r)[13]), "=r"((r)[14]), "=r"((r)[15]), \
          "=r"((r)[16]), "=r"((r)[17]), "=r"((r)[18]), "=r"((r)[19]), \
          "=r"((r)[20]), "=r"((r)[21]), "=r"((r)[22]), "=r"((r)[23]), \
          "=r"((r)[24]), "=r"((r)[25]), "=r"((r)[26]), "=r"((r)[27]), \
          "=r"((r)[28]), "=r"((r)[29]), "=r"((r)[30]), "=r"((r)[31]) \
        : "r"(addr))
#define MBAR_WAIT(mbar, parity) do {                                              \
    asm volatile(                                                                 \
        "{\n\t.reg .pred P1;\n\t"                                                 \
        "WAIT_LOOP_%=:\n\t"                                                       \
        "mbarrier.try_wait.parity.acquire.cta.shared::cta.b64 P1, [%0], %1, 0x989680;\n\t" \
        "@P1 bra.uni WAIT_DONE_%=;\n\t"                                           \
        "bra.uni WAIT_LOOP_%=;\n\t"                                               \
        "WAIT_DONE_%=:\n\t}"                                                      \
        :: "r"((uint32_t)(mbar)), "r"((uint32_t)(parity)) : "memory");            \
} while (0)
static constexpr uint32_t TC_IDESC_G =
    (1u << 4) | (2u << 7) | (2u << 10) | ((256u / 8) << 17) | ((128u / 16) << 24);
#endif

#define TCSTAGE 49152
#define TCB_OFF 16384

__global__ __launch_bounds__(128) void gemm_tc_tf32(
    const float* __restrict__ A, const float* __restrict__ B,
    const float* __restrict__ bias, float* __restrict__ C, int M, int N, int K)
{
#if HAS_TCGEN05
    extern __shared__ char smem[];
    const uint32_t sb = smem_u32(smem);
    const uint32_t ctrl = sb;
    const uint32_t data = (sb + 16 + 1023) & ~1023u;

    const int bm = blockIdx.y * 128;
    const int bn = blockIdx.x * 256;
    const int tid = threadIdx.x;
    const int wid = tid >> 5;
    const int lane = tid & 31;

    if (wid == 0) {
        asm volatile("tcgen05.alloc.cta_group::1.sync.aligned.shared::cta.b32 [%0], %1;"
            :: "r"(ctrl), "r"(256u) : "memory");
        asm volatile("tcgen05.relinquish_alloc_permit.cta_group::1.sync.aligned;");
    }
    __syncthreads();
    uint32_t tmem;
    asm volatile("ld.shared.b32 %0, [%1];" : "=r"(tmem) : "r"(ctrl));
    if (tid == 0)
        asm volatile("mbarrier.init.shared.b64 [%0], %1;" :: "r"(ctrl + 8), "r"(1u) : "memory");
    __syncthreads();

    const int nk = K / 32;

    auto load_chunk = [&](int it) {
        const uint32_t st = data + (uint32_t)(it & 1) * TCSTAGE;
        const int k0 = it * 32;
#pragma unroll
        for (int i = 0; i < 8; i++) {
            int e = tid + i * 128;
            int r = e >> 3, c = e & 7;
            uint32_t byte = (uint32_t)(r * 128 + c * 16);
            uint32_t sw = byte ^ ((byte >> 3) & 0x70u);
            cp_async16s(st + sw, A + (size_t)(bm + r) * K + k0 + c * 4);
        }
#pragma unroll
        for (int i = 0; i < 16; i++) {
            int e = tid + i * 128;
            int r = e >> 3, c = e & 7;
            uint32_t byte = (uint32_t)(r * 128 + c * 16);
            uint32_t sw = byte ^ ((byte >> 3) & 0x70u);
            cp_async16s(st + TCB_OFF + sw, B + (size_t)(bn + r) * K + k0 + c * 4);
        }
        cp_commit();
    };

    load_chunk(0);

    for (int it = 0; it < nk; it++) {
        asm volatile("cp.async.wait_group 0;");
        __syncthreads();
        asm volatile("fence.proxy.async.shared::cta;" ::: "memory");
        if (wid == 0) {
            const uint32_t st = data + (uint32_t)(it & 1) * TCSTAGE;
            uint64_t ad = make_desc_sw128(st);
            uint64_t bd = make_desc_sw128(st + TCB_OFF);
            if (elect_one_pred()) {
#pragma unroll
                for (int ks = 0; ks < 4; ks++)
                    tcgen05_mma_tf32_ss(tmem, ad + ks * 2, bd + ks * 2, TC_IDESC_G,
                                        (it != 0) || (ks != 0));
                asm volatile(
                    "tcgen05.commit.cta_group::1.mbarrier::arrive::one.shared::cluster.b64 [%0];"
                    :: "r"(ctrl + 8) : "memory");
            }
        }
        if (it + 1 < nk) load_chunk(it + 1);
        MBAR_WAIT(ctrl + 8, it & 1);
    }

    asm volatile("tcgen05.fence::after_thread_sync;" ::: "memory");

    {
        float* Crow = C + (size_t)(bm + wid * 32 + lane) * N + bn;
#pragma unroll
        for (int bt = 0; bt < 8; bt++) {
            uint32_t r32[32];
            TC_LD_X32(r32, tmem + bt * 32);
            asm volatile("tcgen05.wait::ld.sync.aligned;" ::: "memory");
            if (bias != nullptr) {
#pragma unroll
                for (int q = 0; q < 8; q++) {
                    float4 bb = *(const float4*)(bias + bn + bt * 32 + q * 4);
                    float4 o;
                    o.x = __uint_as_float(r32[q * 4 + 0]) + bb.x;
                    o.y = __uint_as_float(r32[q * 4 + 1]) + bb.y;
                    o.z = __uint_as_float(r32[q * 4 + 2]) + bb.z;
                    o.w = __uint_as_float(r32[q * 4 + 3]) + bb.w;
                    *(float4*)(Crow + bt * 32 + q * 4) = o;
                }
            } else {
#pragma unroll
                for (int q = 0; q < 8; q++) {
                    float4 o;
                    o.x = __uint_as_float(r32[q * 4 + 0]);
                    o.y = __uint_as_float(r32[q * 4 + 1]);
                    o.z = __uint_as_float(r32[q * 4 + 2]);
                    o.w = __uint_as_float(r32[q * 4 + 3]);
                    *(float4*)(Crow + bt * 32 + q * 4) = o;
                }
            }
        }
    }

    __syncthreads();
    if (tid == 0)
        asm volatile("mbarrier.inval.shared.b64 [%0];" :: "r"(ctrl + 8) : "memory");
    __syncthreads();
    if (wid == 0)
        asm volatile("tcgen05.dealloc.cta_group::1.sync.aligned.b32 %0, %1;"
            :: "r"(tmem), "r"(256u));
#else
    (void)A; (void)B; (void)bias; (void)C; (void)M; (void)N; (void)K;
#endif
}

// ===========================================================================
// wmma GEMM fallback (non-'a' cubin only; bias via separate bias_add)
// ===========================================================================
#define GLDA 36
#define ASTG (128 * GLDA)
#define BSTG (256 * GLDA)

__global__ __launch_bounds__(256) void gemm_wmma_tf32(
    const float* __restrict__ A, const float* __restrict__ B,
    float* __restrict__ C, int M, int N, int K)
{
    if (g_use_tc) return;

    extern __shared__ float sg[];
    float* Asb[2] = { sg,            sg + ASTG };
    float* Bsb[2] = { sg + 2 * ASTG, sg + 2 * ASTG + BSTG };

    const int bm = blockIdx.y * 128;
    const int bn = blockIdx.x * 256;
    const int tid = threadIdx.x;
    const int wid = tid >> 5;
    const int warpM = wid & 1;
    const int warpN = wid >> 1;

    wmma::fragment<wmma::accumulator, 16, 16, 8, float> acc[4][4];
#pragma unroll
    for (int i = 0; i < 4; i++)
#pragma unroll
        for (int j = 0; j < 4; j++) wmma::fill_fragment(acc[i][j], 0.0f);

    const int nk = K / 32;
    auto load_chunk = [&](int it) {
        const int k0 = it * 32;
        float* As = Asb[it & 1];
        float* Bs = Bsb[it & 1];
#pragma unroll
        for (int i = 0; i < 4; i++) {
            int e = tid + i * 256;
            int r = e >> 3, c = (e & 7) * 4;
            cp_async16(As + r * GLDA + c, A + (size_t)(bm + r) * K + k0 + c);
        }
#pragma unroll
        for (int i = 0; i < 8; i++) {
            int e = tid + i * 256;
            int r = e >> 3, c = (e & 7) * 4;
            cp_async16(Bs + r * GLDA + c, B + (size_t)(bn + r) * K + k0 + c);
        }
        cp_commit();
    };
    load_chunk(0);
    for (int it = 0; it < nk; it++) {
        asm volatile("cp.async.wait_group 0;");
        __syncthreads();
        if (it + 1 < nk) load_chunk(it + 1);
        const float* As = Asb[it & 1];
        const float* Bs = Bsb[it & 1];
#pragma unroll
        for (int ks = 0; ks < 4; ks++) {
            wmma::fragment<wmma::matrix_a, 16, 16, 8, wmma::precision::tf32, wmma::row_major> af[4];
            wmma::fragment<wmma::matrix_b, 16, 16, 8, wmma::precision::tf32, wmma::col_major> bf[4];
#pragma unroll
            for (int i = 0; i < 4; i++)
                wmma::load_matrix_sync(af[i], As + (warpM * 64 + i * 16) * GLDA + ks * 8, GLDA);
#pragma unroll
            for (int j = 0; j < 4; j++)
                wmma::load_matrix_sync(bf[j], Bs + (warpN * 64 + j * 16) * GLDA + ks * 8, GLDA);
#pragma unroll
            for (int i = 0; i < 4; i++)
#pragma unroll
                for (int j = 0; j < 4; j++)
                    wmma::mma_sync(acc[i][j], af[i], bf[j], acc[i][j]);
        }
    }
#pragma unroll
    for (int i = 0; i < 4; i++)
#pragma unroll
        for (int j = 0; j < 4; j++)
            wmma::store_matrix_sync(
                C + (size_t)(bm + warpM * 64 + i * 16) * N + bn + warpN * 64 + j * 16,
                acc[i][j], N, wmma::mem_row_major);
}

// ---------------------------------------------------------------------------
// RoPE + bias + transpose; q scaled by 0.125*log2(e); tf32 stores
// ---------------------------------------------------------------------------
__global__ __launch_bounds__(256) void rope_bias_transpose_kernel(
    const float* __restrict__ rpe, const float* __restrict__ bq)
{
    __shared__ float cs[32], sn[32];
    const int m = blockIdx.x;   // l*8 + b
    const int l = m >> 3;
    const int b = m & 7;
    const int tid = threadIdx.x;
    if (tid < 32) {
        float a = rpe[l * 32 + tid];
        cs[tid] = cosf(a);
        sn[tid] = sinf(a);
    }
    __syncthreads();
    const float* src = g_qkv + (size_t)m * 3072;
    for (int r = tid; r < 3072; r += 256) {
        int which = r >> 10;
        int hh = (r >> 6) & 15;
        int d = r & 63;
        float x = src[r] + bq[r];
        float val;
        if (which < 2) {
            float xp = src[r ^ 1] + bq[r ^ 1];
            float c = cs[d & 31];
            float s = sn[d & 31];
            val = x * c + ((d & 1) ? xp : -xp) * s;
        } else {
            val = x;
        }
        if (which == 0) val *= 0.125f * 1.44269504f;   // scale * log2(e)
        float* dst = (which == 0) ? g_q : (which == 1) ? g_k : g_v;
        dst[(((size_t)(b * 16 + hh)) * 1024 + l) * 64 + d] = to_tf32(val);
    }
}

// ===========================================================================
// Flash attention, mma.sync tf32, ONLINE softmax in log2 domain (raw EX2).
// WIDENED: 256 threads (8 warps, 32 rows/warp), 256-row Q tiles, grid (128,4).
// K/V tiles 64 rows double-buffered -> K/V gmem traffic halved vs 128-row tiles.
// ===========================================================================
#define AKL 68
#define AVL 72
#define QSTG2 (256 * AKL)
#define KSTG (64 * AKL)
#define VSTG (64 * AVL)
#define ATT_SMEM2 ((QSTG2 + 2 * KSTG + 2 * VSTG) * (int)sizeof(float))   // 141312

__global__ __launch_bounds__(256) void attn_tf32_reg()
{
    extern __shared__ float sm[];
    float* Qs = sm;                                     // 256 x 68 (doubles as P)
    float* Ksb[2] = { sm + QSTG2,            sm + QSTG2 + KSTG };
    float* Vsb[2] = { sm + QSTG2 + 2 * KSTG, sm + QSTG2 + 2 * KSTG + VSTG };

    const int bh = blockIdx.x;
    const int b = bh >> 4;
    const int h = bh & 15;
    const int qt = blockIdx.y;                          // 0..3, 256 rows each
    const int tid = threadIdx.x;
    const int w = tid >> 5;                             // 0..7
    const int lane = tid & 31;
    const int g = lane >> 2;
    const int t = lane & 3;

    const float* Kg = g_k + (size_t)bh * 65536;
    const float* Vg = g_v + (size_t)bh * 65536;

    auto load_kv = [&](int kt) {
        float* Kd = Ksb[kt & 1];
        float* Vd = Vsb[kt & 1];
        const size_t off = (size_t)kt * 4096;
#pragma unroll
        for (int i = 0; i < 4; i++) {
            int e = tid + i * 256;
            int r = e >> 4, c = (e & 15) * 4;
            cp_async16(Kd + r * AKL + c, Kg + off + (size_t)r * 64 + c);
            cp_async16(Vd + r * AVL + c, Vg + off + (size_t)r * 64 + c);
        }
        cp_commit();
    };
    load_kv(0);

    {
        const float* Qg = g_q + ((size_t)bh * 1024 + qt * 256) * 64;
#pragma unroll
        for (int i = 0; i < 16; i++) {
            int e = tid + i * 256;                      // 0..4095 float4 slots
            int r = e >> 4, c = (e & 15) * 4;
            float4 v = *(const float4*)(Qg + r * 64 + c);
            *(float4*)(Qs + r * AKL + c) = v;
        }
    }
    __syncthreads();

    unsigned qa[2][8][4];
#pragma unroll
    for (int rf = 0; rf < 2; rf++) {
        const float* Qw = Qs + (w * 32 + rf * 16) * AKL;
#pragma unroll
        for (int ks = 0; ks < 8; ks++) {
            qa[rf][ks][0] = __float_as_uint(Qw[g * AKL + ks * 8 + t]);
            qa[rf][ks][1] = __float_as_uint(Qw[(g + 8) * AKL + ks * 8 + t]);
            qa[rf][ks][2] = __float_as_uint(Qw[g * AKL + ks * 8 + t + 4]);
            qa[rf][ks][3] = __float_as_uint(Qw[(g + 8) * AKL + ks * 8 + t + 4]);
        }
    }
    __syncthreads();   // Qs becomes P strips

    float o[2][8][4];
#pragma unroll
    for (int rf = 0; rf < 2; rf++)
#pragma unroll
        for (int j = 0; j < 8; j++)
            o[rf][j][0] = o[rf][j][1] = o[rf][j][2] = o[rf][j][3] = 0.f;
    float mr[2][2] = {{-1e30f, -1e30f}, {-1e30f, -1e30f}};
    float ll[2][2] = {{0.f, 0.f}, {0.f, 0.f}};

    const int qrow = qt * 256 + w * 32 + g;
    float* Pw = Qs + (w * 32) * AKL;

    for (int kt = 0; kt < 16; kt++) {
        asm volatile("cp.async.wait_group 0;");
        __syncthreads();
        if (kt + 1 < 16) load_kv(kt + 1);

        const float* Ks = Ksb[kt & 1];
        const float* Vs = Vsb[kt & 1];

        // S = Q K^T (scores already in log2 domain via q pre-scale)
        float s[2][8][4];
#pragma unroll
        for (int j = 0; j < 8; j++) {
            s[0][j][0] = s[0][j][1] = s[0][j][2] = s[0][j][3] = 0.f;
            s[1][j][0] = s[1][j][1] = s[1][j][2] = s[1][j][3] = 0.f;
#pragma unroll
            for (int ks = 0; ks < 8; ks++) {
                unsigned b0 = __float_as_uint(Ks[(j * 8 + g) * AKL + ks * 8 + t]);
                unsigned b1 = __float_as_uint(Ks[(j * 8 + g) * AKL + ks * 8 + t + 4]);
                mma8(s[0][j], qa[0][ks], b0, b1);
                mma8(s[1][j], qa[1][ks], b0, b1);
            }
        }

        // mask + online softmax (log2 domain, raw EX2)
        const size_t mbi = ((size_t)b * 16 + kt) * 1024;
#pragma unroll
        for (int rf = 0; rf < 2; rf++) {
            const unsigned long long mb0 = g_maskbits[mbi + qrow + rf * 16];
            const unsigned long long mb1 = g_maskbits[mbi + qrow + rf * 16 + 8];
#pragma unroll
            for (int j = 0; j < 8; j++) {
                int c0 = j * 8 + t * 2;
                s[rf][j][0] = ((mb0 >> c0) & 1ULL) ? s[rf][j][0] : -1e30f;
                s[rf][j][1] = ((mb0 >> (c0 + 1)) & 1ULL) ? s[rf][j][1] : -1e30f;
                s[rf][j][2] = ((mb1 >> c0) & 1ULL) ? s[rf][j][2] : -1e30f;
                s[rf][j][3] = ((mb1 >> (c0 + 1)) & 1ULL) ? s[rf][j][3] : -1e30f;
            }
            float rm0 = -1e30f, rm1 = -1e30f;
#pragma unroll
            for (int j = 0; j < 8; j++) {
                rm0 = fmaxf(rm0, fmaxf(s[rf][j][0], s[rf][j][1]));
                rm1 = fmaxf(rm1, fmaxf(s[rf][j][2], s[rf][j][3]));
            }
            rm0 = fmaxf(rm0, __shfl_xor_sync(0xffffffffu, rm0, 1));
            rm0 = fmaxf(rm0, __shfl_xor_sync(0xffffffffu, rm0, 2));
            rm1 = fmaxf(rm1, __shfl_xor_sync(0xffffffffu, rm1, 1));
            rm1 = fmaxf(rm1, __shfl_xor_sync(0xffffffffu, rm1, 2));
            float mn0 = fmaxf(mr[rf][0], rm0), mn1 = fmaxf(mr[rf][1], rm1);
            float al0 = ex2_fast(mr[rf][0] - mn0), al1 = ex2_fast(mr[rf][1] - mn1);
            float sum0 = 0.f, sum1 = 0.f;
            float* Prf = Pw + rf * 16 * AKL;
#pragma unroll
            for (int j = 0; j < 8; j++) {
                float p0 = ex2_fast(s[rf][j][0] - mn0);
                float p1 = ex2_fast(s[rf][j][1] - mn0);
                float p2 = ex2_fast(s[rf][j][2] - mn1);
                float p3 = ex2_fast(s[rf][j][3] - mn1);
                sum0 += p0 + p1; sum1 += p2 + p3;
                *(float2*)(Prf + g * AKL + j * 8 + t * 2) =
                    make_float2(to_tf32(p0), to_tf32(p1));
                *(float2*)(Prf + (g + 8) * AKL + j * 8 + t * 2) =
                    make_float2(to_tf32(p2), to_tf32(p3));
            }
            sum0 += __shfl_xor_sync(0xffffffffu, sum0, 1);
            sum0 += __shfl_xor_sync(0xffffffffu, sum0, 2);
            sum1 += __shfl_xor_sync(0xffffffffu, sum1, 1);
            sum1 += __shfl_xor_sync(0xffffffffu, sum1, 2);
            ll[rf][0] = ll[rf][0] * al0 + sum0; mr[rf][0] = mn0;
            ll[rf][1] = ll[rf][1] * al1 + sum1; mr[rf][1] = mn1;
#pragma unroll
            for (int j = 0; j < 8; j++) {
                o[rf][j][0] *= al0; o[rf][j][1] *= al0;
                o[rf][j][2] *= al1; o[rf][j][3] *= al1;
            }
        }
        __syncwarp();

        // O += P V
#pragma unroll
        for (int ks = 0; ks < 8; ks++) {
            unsigned pa[2][4];
#pragma unroll
            for (int rf = 0; rf < 2; rf++) {
                const float* Prf = Pw + rf * 16 * AKL;
                pa[rf][0] = __float_as_uint(Prf[g * AKL + ks * 8 + t]);
                pa[rf][1] = __float_as_uint(Prf[(g + 8) * AKL + ks * 8 + t]);
                pa[rf][2] = __float_as_uint(Prf[g * AKL + ks * 8 + t + 4]);
                pa[rf][3] = __float_as_uint(Prf[(g + 8) * AKL + ks * 8 + t + 4]);
            }
#pragma unroll
            for (int j = 0; j < 8; j++) {
                unsigned b0 = __float_as_uint(Vs[(ks * 8 + t) * AVL + j * 8 + g]);
                unsigned b1 = __float_as_uint(Vs[(ks * 8 + t + 4) * AVL + j * 8 + g]);
                mma8(o[0][j], pa[0], b0, b1);
                mma8(o[1][j], pa[1], b0, b1);
            }
        }
        __syncwarp();
    }

#pragma unroll
    for (int rf = 0; rf < 2; rf++) {
        const float inv0 = 1.f / ll[rf][0], inv1 = 1.f / ll[rf][1];
        const int lq0 = qt * 256 + w * 32 + rf * 16 + g;
#pragma unroll
        for (int j = 0; j < 8; j++) {
            *(float2*)(g_attn + ((size_t)lq0 * 8 + b) * 1024 + h * 64 + j * 8 + t * 2) =
                make_float2(to_tf32(o[rf][j][0] * inv0), to_tf32(o[rf][j][1] * inv0));
            *(float2*)(g_attn + ((size_t)(lq0 + 8) * 8 + b) * 1024 + h * 64 + j * 8 + t * 2) =
                make_float2(to_tf32(o[rf][j][2] * inv1), to_tf32(o[rf][j][3] * inv1));
        }
    }
}

// ---------------------------------------------------------------------------
// Final bias add — only needed on the wmma fallback path (tc path fuses bias)
// ---------------------------------------------------------------------------
__global__ __launch_bounds__(256) void bias_add_kernel(float* __restrict__ out,
                                                       const float* __restrict__ bo)
{
    if (g_use_tc) return;
    const int m = blockIdx.x;
    const int c = threadIdx.x * 4;
    float4 o = *(float4*)(out + (size_t)m * 1024 + c);
    float4 bb = *(const float4*)(bo + c);
    o.x += bb.x; o.y += bb.y; o.z += bb.z; o.w += bb.w;
    *(float4*)(out + (size_t)m * 1024 + c) = o;
}

// ---------------------------------------------------------------------------
// Launch
// ---------------------------------------------------------------------------
extern "C" void kernel_launch(void* const* d_in, const int* in_sizes, int n_in,
                              void* d_out, int out_size)
{
    const float* hs   = (const float*)d_in[0];
    const float* rpe  = (const float*)d_in[1];
    const void* maskp = d_in[2];
    const float* Wqkv = (const float*)d_in[3];
    const float* bqkv = (const float*)d_in[4];
    const float* Wo   = (const float*)d_in[5];
    const float* bo   = (const float*)d_in[6];
    float* out        = (float*)d_out;

    float *hs_p, *wqkv_p, *wo_p, *qkv_p, *attn_p;
    cudaGetSymbolAddress((void**)&hs_p, g_hs);
    cudaGetSymbolAddress((void**)&wqkv_p, g_wqkv);
    cudaGetSymbolAddress((void**)&wo_p, g_wo);
    cudaGetSymbolAddress((void**)&qkv_p, g_qkv);
    cudaGetSymbolAddress((void**)&attn_p, g_attn);

    probe_tc_kernel<<<1, 32>>>();
    detect_mask_mode_kernel<<<1, 256>>>((const unsigned char*)maskp);
    convert_mask_bits_kernel<<<131072 / 256, 256>>>(maskp);
    tf32_round_kernel<<<(8388608 / 4) / 256, 256>>>(hs_p, hs, 8388608 / 4);
    tf32_round_kernel<<<(3145728 / 4) / 256, 256>>>(wqkv_p, Wqkv, 3145728 / 4);
    tf32_round_kernel<<<(1048576 / 4) / 256, 256>>>(wo_p, Wo, 1048576 / 4);

    const int tc_smem = 2048 + 2 * TCSTAGE;
    const int wm_smem = 2 * (ASTG + BSTG) * (int)sizeof(float);
    cudaFuncSetAttribute(gemm_tc_tf32,
                         cudaFuncAttributeMaxDynamicSharedMemorySize, tc_smem);
    cudaFuncSetAttribute(gemm_wmma_tf32,
                         cudaFuncAttributeMaxDynamicSharedMemorySize, wm_smem);

    // Stage 1: QKV projection (dual path; no bias — rope adds bqkv)
    {
        dim3 grid(3072 / 256, 8192 / 128);
        gemm_tc_tf32<<<grid, 128, tc_smem>>>(hs_p, wqkv_p, nullptr, qkv_p, 8192, 3072, 1024);
        gemm_wmma_tf32<<<grid, 256, wm_smem>>>(hs_p, wqkv_p, qkv_p, 8192, 3072, 1024);
    }

    // Stage 2: RoPE + bqkv + transpose
    rope_bias_transpose_kernel<<<8192, 256>>>(rpe, bqkv);

    // Stage 3: attention (widened: 256 threads, 256-row Q tiles)
    {
        cudaFuncSetAttribute(attn_tf32_reg,
                             cudaFuncAttributeMaxDynamicSharedMemorySize, ATT_SMEM2);
        dim3 grid(128, 4);
        attn_tf32_reg<<<grid, 256, ATT_SMEM2>>>();
    }

    // Stage 4: output projection (tc fuses bo; fallback adds it separately)
    {
        dim3 grid(1024 / 256, 8192 / 128);
        gemm_tc_tf32<<<grid, 128, tc_smem>>>(attn_p, wo_p, bo, out, 8192, 1024, 1024);
        gemm_wmma_tf32<<<grid, 256, wm_smem>>>(attn_p, wo_p, out, 8192, 1024, 1024);
        bias_add_kernel<<<8192, 256>>>(out, bo);
    }
}

// round 14
// speedup vs baseline: 1.0840x; 1.0840x over previous
#include <cuda_runtime.h>
#include <mma.h>
#include <cstdint>

using namespace nvcuda;

// ---------------------------------------------------------------------------
// VisionSdpaAttention — v11: R9 champion shape + free micro-wins only
//   tcgen05 GEMMs (bias fused) + mma.sync attention (128 thr, 2 CTA/SM,
//   online softmax in log2 domain on raw EX2)
//   L=1024, B=8, C=1024, H=16, D=64
// ---------------------------------------------------------------------------

#if defined(__CUDA_ARCH_FEAT_SM103_ALL) || defined(__CUDA_ARCH_FEAT_SM100_ALL)
#define HAS_TCGEN05 1
#else
#define HAS_TCGEN05 0
#endif

__device__ float g_hs[8388608];               // tf32-rounded hidden_states
__device__ float g_wqkv[3145728];             // tf32-rounded Wqkv
__device__ float g_wo[1048576];               // tf32-rounded Wo
__device__ float g_qkv[25165824];             // (L*B, 3C)
__device__ float g_q[8388608];                // (B,H,L,D) tf32, scaled 0.125*log2(e)
__device__ float g_k[8388608];
__device__ float g_v[8388608];
__device__ float g_attn[8388608];             // (L*B, C) tf32-rounded
__device__ unsigned long long g_maskbits[131072];  // [B][16 kt][1024 rows]
__device__ int g_mask_mode;
__device__ int g_use_tc;

__device__ __forceinline__ float to_tf32(float x) {
    unsigned int u;
    asm("cvt.rna.tf32.f32 %0, %1;" : "=r"(u) : "f"(x));
    return __uint_as_float(u);
}
__device__ __forceinline__ float ex2_fast(float x) {
    float r;
    asm("ex2.approx.ftz.f32 %0, %1;" : "=f"(r) : "f"(x));
    return r;
}
__device__ __forceinline__ void cp_async16(void* sptr, const void* gptr) {
    unsigned s = (unsigned)__cvta_generic_to_shared(sptr);
    asm volatile("cp.async.cg.shared.global [%0], [%1], 16;" :: "r"(s), "l"(gptr));
}
__device__ __forceinline__ void cp_async16s(uint32_t saddr, const void* gptr) {
    asm volatile("cp.async.cg.shared.global [%0], [%1], 16;" :: "r"(saddr), "l"(gptr));
}
__device__ __forceinline__ void cp_commit() {
    asm volatile("cp.async.commit_group;");
}
__device__ __forceinline__ void mma8(float* c, const unsigned* a, unsigned b0, unsigned b1) {
    asm volatile(
        "mma.sync.aligned.m16n8k8.row.col.f32.tf32.tf32.f32 "
        "{%0,%1,%2,%3},{%4,%5,%6,%7},{%8,%9},{%0,%1,%2,%3};"
        : "+f"(c[0]), "+f"(c[1]), "+f"(c[2]), "+f"(c[3])
        : "r"(a[0]), "r"(a[1]), "r"(a[2]), "r"(a[3]), "r"(b0), "r"(b1));
}
__device__ __forceinline__ uint32_t smem_u32(const void* p) {
    return (uint32_t)__cvta_generic_to_shared(p);
}

__global__ void probe_tc_kernel() { if (threadIdx.x == 0) g_use_tc = HAS_TCGEN05; }

// ---------------------------------------------------------------------------
// tf32 rounding copy
// ---------------------------------------------------------------------------
__global__ __launch_bounds__(256) void tf32_round_kernel(
    float* __restrict__ dst, const float* __restrict__ src, int n4)
{
    int i = blockIdx.x * 256 + threadIdx.x;
    if (i >= n4) return;
    float4 v = *((const float4*)src + i);
    v.x = to_tf32(v.x); v.y = to_tf32(v.y);
    v.z = to_tf32(v.z); v.w = to_tf32(v.w);
    *((float4*)dst + i) = v;
}

// ---------------------------------------------------------------------------
// Mask detection + bitpack -> layout [b][kt][row]
// ---------------------------------------------------------------------------
__global__ void detect_mask_mode_kernel(const unsigned char* __restrict__ m)
{
    __shared__ int s1, s23;
    const int tid = threadIdx.x;
    if (tid == 0) { s1 = 0; s23 = 0; }
    __syncthreads();
    bool o1 = false, o23 = false;
    for (int i = tid * 4; i < 16384; i += 1024) {
        if (m[i + 1] != 0) o1 = true;
        if (m[i + 2] != 0 || m[i + 3] != 0) o23 = true;
    }
    if (o1) atomicOr(&s1, 1);
    if (o23) atomicOr(&s23, 1);
    __syncthreads();
    if (tid == 0) g_mask_mode = s1 ? 0 : (s23 ? 2 : 1);
}

__global__ __launch_bounds__(256) void convert_mask_bits_kernel(const void* __restrict__ mp)
{
    const int idx = blockIdx.x * 256 + threadIdx.x;   // input word: (b*1024+row)*16+kt
    const int mode = g_mask_mode;
    unsigned long long bits = 0ULL;
    const size_t base = (size_t)idx * 64;
    if (mode == 0) {
        const uint4* p = (const uint4*)((const unsigned char*)mp + base);
#pragma unroll
        for (int wrd = 0; wrd < 4; wrd++) {
            uint4 v = p[wrd];
            unsigned ws[4] = {v.x, v.y, v.z, v.w};
#pragma unroll
            for (int q = 0; q < 4; q++)
#pragma unroll
                for (int by = 0; by < 4; by++)
                    if ((ws[q] >> (by * 8)) & 0xffu)
                        bits |= 1ULL << (wrd * 16 + q * 4 + by);
        }
    } else if (mode == 1) {
        const int* p = (const int*)mp + base;
#pragma unroll 8
        for (int j = 0; j < 64; j++)
            if (p[j] != 0) bits |= 1ULL << j;
    } else {
        const float* p = (const float*)mp + base;
#pragma unroll 8
        for (int j = 0; j < 64; j++)
            if (p[j] != 0.0f) bits |= 1ULL << j;
    }
    const int b = idx >> 14;
    const int row = (idx >> 4) & 1023;
    const int kt = idx & 15;
    g_maskbits[((size_t)b * 16 + kt) * 1024 + row] = bits;
}

// ===========================================================================
// tcgen05 helpers + GEMM (verified in R9; bias fused in epilogue)
// ===========================================================================
#if HAS_TCGEN05
__device__ __forceinline__ uint32_t elect_one_pred() {
    uint32_t pred;
    asm volatile(
        "{\n\t.reg .pred p;\n\telect.sync _|p, 0xFFFFFFFF;\n\t"
        "selp.b32 %0, 1, 0, p;\n\t}" : "=r"(pred));
    return pred;
}
static __device__ __forceinline__ uint64_t make_desc_sw128(uint32_t addr) {
    return ((uint64_t)2u << 61) | ((uint64_t)1u << 46) | ((uint64_t)64u << 32)
         | ((uint64_t)1u << 16) | ((uint64_t)(addr >> 4) & 0x3FFFu);
}
__device__ __forceinline__ void tcgen05_mma_tf32_ss(
    uint32_t d_tmem, uint64_t a_desc, uint64_t b_desc, uint32_t idesc, bool enable_d)
{
    uint32_t en = enable_d ? 1u : 0u;
    asm volatile(
        "{\n\t.reg .pred p;\n\t"
        "setp.ne.u32 p, %5, 0;\n\t"
        "tcgen05.mma.cta_group::1.kind::tf32 [%0], %1, %2, %3, {%4, %4, %4, %4}, p;\n\t"
        "}"
        :: "r"(d_tmem), "l"(a_desc), "l"(b_desc), "r"(idesc), "r"(0u), "r"(en)
        : "memory");
}
#define TC_LD_X32(r, addr) \
    asm volatile( \
        "tcgen05.ld.sync.aligned.32x32b.x32.b32 " \
        "{%0, %1, %2, %3, %4, %5, %6, %7, " \
        " %8, %9, %10, %11, %12, %13, %14, %15, " \
        " %16, %17, %18, %19, %20, %21, %22, %23, " \
        " %24, %25, %26, %27, %28, %29, %30, %31}, [%32];" \
        : "=r"((r)[0]),  "=r"((r)[1]),  "=r"((r)[2]),  "=r"((r)[3]), \
          "=r"((r)[4]),  "=r"((r)[5]),  "=r"((r)[6]),  "=r"((r)[7]), \
          "=r"((r)[8]),  "=r"((r)[9]),  "=r"((r)[10]), "=r"((r)[11]), \
          "=r"((r)[12]), "=r"((r)[13]), "=r"((r)[14]), "=r"((r)[15]), \
          "=r"((r)[16]), "=r"((r)[17]), "=r"((r)[18]), "=r"((r)[19]), \
          "=r"((r)[20]), "=r"((r)[21]), "=r"((r)[22]), "=r"((r)[23]), \
          "=r"((r)[24]), "=r"((r)[25]), "=r"((r)[26]), "=r"((r)[27]), \
          "=r"((r)[28]), "=r"((r)[29]), "=r"((r)[30]), "=r"((r)[31]) \
        : "r"(addr))
#define MBAR_WAIT(mbar, parity) do {                                              \
    asm volatile(                                                                 \
        "{\n\t.reg .pred P1;\n\t"                                                 \
        "WAIT_LOOP_%=:\n\t"                                                       \
        "mbarrier.try_wait.parity.acquire.cta.shared::cta.b64 P1, [%0], %1, 0x989680;\n\t" \
        "@P1 bra.uni WAIT_DONE_%=;\n\t"                                           \
        "bra.uni WAIT_LOOP_%=;\n\t"                                               \
        "WAIT_DONE_%=:\n\t}"                                                      \
        :: "r"((uint32_t)(mbar)), "r"((uint32_t)(parity)) : "memory");            \
} while (0)
static constexpr uint32_t TC_IDESC_G =
    (1u << 4) | (2u << 7) | (2u << 10) | ((256u / 8) << 17) | ((128u / 16) << 24);
#endif

#define TCSTAGE 49152
#define TCB_OFF 16384

__global__ __launch_bounds__(128) void gemm_tc_tf32(
    const float* __restrict__ A, const float* __restrict__ B,
    const float* __restrict__ bias, float* __restrict__ C, int M, int N, int K)
{
#if HAS_TCGEN05
    extern __shared__ char smem[];
    const uint32_t sb = smem_u32(smem);
    const uint32_t ctrl = sb;
    const uint32_t data = (sb + 16 + 1023) & ~1023u;

    const int bm = blockIdx.y * 128;
    const int bn = blockIdx.x * 256;
    const int tid = threadIdx.x;
    const int wid = tid >> 5;
    const int lane = tid & 31;

    if (wid == 0) {
        asm volatile("tcgen05.alloc.cta_group::1.sync.aligned.shared::cta.b32 [%0], %1;"
            :: "r"(ctrl), "r"(256u) : "memory");
        asm volatile("tcgen05.relinquish_alloc_permit.cta_group::1.sync.aligned;");
    }
    __syncthreads();
    uint32_t tmem;
    asm volatile("ld.shared.b32 %0, [%1];" : "=r"(tmem) : "r"(ctrl));
    if (tid == 0)
        asm volatile("mbarrier.init.shared.b64 [%0], %1;" :: "r"(ctrl + 8), "r"(1u) : "memory");
    __syncthreads();

    const int nk = K / 32;

    auto load_chunk = [&](int it) {
        const uint32_t st = data + (uint32_t)(it & 1) * TCSTAGE;
        const int k0 = it * 32;
#pragma unroll
        for (int i = 0; i < 8; i++) {
            int e = tid + i * 128;
            int r = e >> 3, c = e & 7;
            uint32_t byte = (uint32_t)(r * 128 + c * 16);
            uint32_t sw = byte ^ ((byte >> 3) & 0x70u);
            cp_async16s(st + sw, A + (size_t)(bm + r) * K + k0 + c * 4);
        }
#pragma unroll
        for (int i = 0; i < 16; i++) {
            int e = tid + i * 128;
            int r = e >> 3, c = e & 7;
            uint32_t byte = (uint32_t)(r * 128 + c * 16);
            uint32_t sw = byte ^ ((byte >> 3) & 0x70u);
            cp_async16s(st + TCB_OFF + sw, B + (size_t)(bn + r) * K + k0 + c * 4);
        }
        cp_commit();
    };

    load_chunk(0);

    for (int it = 0; it < nk; it++) {
        asm volatile("cp.async.wait_group 0;");
        __syncthreads();
        asm volatile("fence.proxy.async.shared::cta;" ::: "memory");
        if (wid == 0) {
            const uint32_t st = data + (uint32_t)(it & 1) * TCSTAGE;
            uint64_t ad = make_desc_sw128(st);
            uint64_t bd = make_desc_sw128(st + TCB_OFF);
            if (elect_one_pred()) {
#pragma unroll
                for (int ks = 0; ks < 4; ks++)
                    tcgen05_mma_tf32_ss(tmem, ad + ks * 2, bd + ks * 2, TC_IDESC_G,
                                        (it != 0) || (ks != 0));
                asm volatile(
                    "tcgen05.commit.cta_group::1.mbarrier::arrive::one.shared::cluster.b64 [%0];"
                    :: "r"(ctrl + 8) : "memory");
            }
        }
        if (it + 1 < nk) load_chunk(it + 1);
        MBAR_WAIT(ctrl + 8, it & 1);
    }

    asm volatile("tcgen05.fence::after_thread_sync;" ::: "memory");

    {
        float* Crow = C + (size_t)(bm + wid * 32 + lane) * N + bn;
#pragma unroll
        for (int bt = 0; bt < 8; bt++) {
            uint32_t r32[32];
            TC_LD_X32(r32, tmem + bt * 32);
            asm volatile("tcgen05.wait::ld.sync.aligned;" ::: "memory");
            if (bias != nullptr) {
#pragma unroll
                for (int q = 0; q < 8; q++) {
                    float4 bb = *(const float4*)(bias + bn + bt * 32 + q * 4);
                    float4 o;
                    o.x = __uint_as_float(r32[q * 4 + 0]) + bb.x;
                    o.y = __uint_as_float(r32[q * 4 + 1]) + bb.y;
                    o.z = __uint_as_float(r32[q * 4 + 2]) + bb.z;
                    o.w = __uint_as_float(r32[q * 4 + 3]) + bb.w;
                    *(float4*)(Crow + bt * 32 + q * 4) = o;
                }
            } else {
#pragma unroll
                for (int q = 0; q < 8; q++) {
                    float4 o;
                    o.x = __uint_as_float(r32[q * 4 + 0]);
                    o.y = __uint_as_float(r32[q * 4 + 1]);
                    o.z = __uint_as_float(r32[q * 4 + 2]);
                    o.w = __uint_as_float(r32[q * 4 + 3]);
                    *(float4*)(Crow + bt * 32 + q * 4) = o;
                }
            }
        }
    }

    __syncthreads();
    if (tid == 0)
        asm volatile("mbarrier.inval.shared.b64 [%0];" :: "r"(ctrl + 8) : "memory");
    __syncthreads();
    if (wid == 0)
        asm volatile("tcgen05.dealloc.cta_group::1.sync.aligned.b32 %0, %1;"
            :: "r"(tmem), "r"(256u));
#else
    (void)A; (void)B; (void)bias; (void)C; (void)M; (void)N; (void)K;
#endif
}

// ===========================================================================
// wmma GEMM fallback (non-'a' cubin only)
// ===========================================================================
#define GLDA 36
#define ASTG (128 * GLDA)
#define BSTG (256 * GLDA)

__global__ __launch_bounds__(256) void gemm_wmma_tf32(
    const float* __restrict__ A, const float* __restrict__ B,
    float* __restrict__ C, int M, int N, int K)
{
    if (g_use_tc) return;

    extern __shared__ float sg[];
    float* Asb[2] = { sg,            sg + ASTG };
    float* Bsb[2] = { sg + 2 * ASTG, sg + 2 * ASTG + BSTG };

    const int bm = blockIdx.y * 128;
    const int bn = blockIdx.x * 256;
    const int tid = threadIdx.x;
    const int wid = tid >> 5;
    const int warpM = wid & 1;
    const int warpN = wid >> 1;

    wmma::fragment<wmma::accumulator, 16, 16, 8, float> acc[4][4];
#pragma unroll
    for (int i = 0; i < 4; i++)
#pragma unroll
        for (int j = 0; j < 4; j++) wmma::fill_fragment(acc[i][j], 0.0f);

    const int nk = K / 32;
    auto load_chunk = [&](int it) {
        const int k0 = it * 32;
        float* As = Asb[it & 1];
        float* Bs = Bsb[it & 1];
#pragma unroll
        for (int i = 0; i < 4; i++) {
            int e = tid + i * 256;
            int r = e >> 3, c = (e & 7) * 4;
            cp_async16(As + r * GLDA + c, A + (size_t)(bm + r) * K + k0 + c);
        }
#pragma unroll
        for (int i = 0; i < 8; i++) {
            int e = tid + i * 256;
            int r = e >> 3, c = (e & 7) * 4;
            cp_async16(Bs + r * GLDA + c, B + (size_t)(bn + r) * K + k0 + c);
        }
        cp_commit();
    };
    load_chunk(0);
    for (int it = 0; it < nk; it++) {
        asm volatile("cp.async.wait_group 0;");
        __syncthreads();
        if (it + 1 < nk) load_chunk(it + 1);
        const float* As = Asb[it & 1];
        const float* Bs = Bsb[it & 1];
#pragma unroll
        for (int ks = 0; ks < 4; ks++) {
            wmma::fragment<wmma::matrix_a, 16, 16, 8, wmma::precision::tf32, wmma::row_major> af[4];
            wmma::fragment<wmma::matrix_b, 16, 16, 8, wmma::precision::tf32, wmma::col_major> bf[4];
#pragma unroll
            for (int i = 0; i < 4; i++)
                wmma::load_matrix_sync(af[i], As + (warpM * 64 + i * 16) * GLDA + ks * 8, GLDA);
#pragma unroll
            for (int j = 0; j < 4; j++)
                wmma::load_matrix_sync(bf[j], Bs + (warpN * 64 + j * 16) * GLDA + ks * 8, GLDA);
#pragma unroll
            for (int i = 0; i < 4; i++)
#pragma unroll
                for (int j = 0; j < 4; j++)
                    wmma::mma_sync(acc[i][j], af[i], bf[j], acc[i][j]);
        }
    }
#pragma unroll
    for (int i = 0; i < 4; i++)
#pragma unroll
        for (int j = 0; j < 4; j++)
            wmma::store_matrix_sync(
                C + (size_t)(bm + warpM * 64 + i * 16) * N + bn + warpN * 64 + j * 16,
                acc[i][j], N, wmma::mem_row_major);
}

// ---------------------------------------------------------------------------
// RoPE + bias + transpose; q scaled by 0.125*log2(e); tf32 stores
// ---------------------------------------------------------------------------
__global__ __launch_bounds__(256) void rope_bias_transpose_kernel(
    const float* __restrict__ rpe, const float* __restrict__ bq)
{
    __shared__ float cs[32], sn[32];
    const int m = blockIdx.x;   // l*8 + b
    const int l = m >> 3;
    const int b = m & 7;
    const int tid = threadIdx.x;
    if (tid < 32) {
        float a = rpe[l * 32 + tid];
        cs[tid] = cosf(a);
        sn[tid] = sinf(a);
    }
    __syncthreads();
    const float* src = g_qkv + (size_t)m * 3072;
    for (int r = tid; r < 3072; r += 256) {
        int which = r >> 10;
        int hh = (r >> 6) & 15;
        int d = r & 63;
        float x = src[r] + bq[r];
        float val;
        if (which < 2) {
            float xp = src[r ^ 1] + bq[r ^ 1];
            float c = cs[d & 31];
            float s = sn[d & 31];
            val = x * c + ((d & 1) ? xp : -xp) * s;
        } else {
            val = x;
        }
        if (which == 0) val *= 0.125f * 1.44269504f;   // scale * log2(e)
        float* dst = (which == 0) ? g_q : (which == 1) ? g_k : g_v;
        dst[(((size_t)(b * 16 + hh)) * 1024 + l) * 64 + d] = to_tf32(val);
    }
}

// ===========================================================================
// Flash attention — R9 champion shape: 128 threads (4 warps, 32 rows/warp),
// 128-row Q tiles, grid (128, 8), 2 CTAs/SM. Online softmax in log2 domain
// with raw EX2; coalesced mask layout [b][kt][row].
// ===========================================================================
#define AKL 68
#define AVL 72
#define QSTG (128 * AKL)
#define KSTG (64 * AKL)
#define VSTG (64 * AVL)
#define ATT_SMEM ((QSTG + 2 * KSTG + 2 * VSTG) * (int)sizeof(float))   // 106496

__global__ __launch_bounds__(128) void attn_tf32_reg()
{
    extern __shared__ float sm[];
    float* Qs = sm;
    float* Ksb[2] = { sm + QSTG,            sm + QSTG + KSTG };
    float* Vsb[2] = { sm + QSTG + 2 * KSTG, sm + QSTG + 2 * KSTG + VSTG };

    const int bh = blockIdx.x;
    const int b = bh >> 4;
    const int h = bh & 15;
    const int qt = blockIdx.y;
    const int tid = threadIdx.x;
    const int w = tid >> 5;
    const int lane = tid & 31;
    const int g = lane >> 2;
    const int t = lane & 3;

    const float* Kg = g_k + (size_t)bh * 65536;
    const float* Vg = g_v + (size_t)bh * 65536;

    auto load_kv = [&](int kt) {
        float* Kd = Ksb[kt & 1];
        float* Vd = Vsb[kt & 1];
        const size_t off = (size_t)kt * 4096;
#pragma unroll
        for (int i = 0; i < 8; i++) {
            int e = tid + i * 128;
            int r = e >> 4, c = (e & 15) * 4;
            cp_async16(Kd + r * AKL + c, Kg + off + (size_t)r * 64 + c);
            cp_async16(Vd + r * AVL + c, Vg + off + (size_t)r * 64 + c);
        }
        cp_commit();
    };
    load_kv(0);

    {
        const float* Qg = g_q + ((size_t)bh * 1024 + qt * 128) * 64;
#pragma unroll
        for (int i = 0; i < 16; i++) {
            int e = tid + i * 128;
            int r = e >> 4, c = (e & 15) * 4;
            float4 v = *(const float4*)(Qg + r * 64 + c);
            *(float4*)(Qs + r * AKL + c) = v;
        }
    }
    __syncthreads();

    unsigned qa[2][8][4];
#pragma unroll
    for (int rf = 0; rf < 2; rf++) {
        const float* Qw = Qs + (w * 32 + rf * 16) * AKL;
#pragma unroll
        for (int ks = 0; ks < 8; ks++) {
            qa[rf][ks][0] = __float_as_uint(Qw[g * AKL + ks * 8 + t]);
            qa[rf][ks][1] = __float_as_uint(Qw[(g + 8) * AKL + ks * 8 + t]);
            qa[rf][ks][2] = __float_as_uint(Qw[g * AKL + ks * 8 + t + 4]);
            qa[rf][ks][3] = __float_as_uint(Qw[(g + 8) * AKL + ks * 8 + t + 4]);
        }
    }
    __syncthreads();   // Qs becomes P strips

    float o[2][8][4];
#pragma unroll
    for (int rf = 0; rf < 2; rf++)
#pragma unroll
        for (int j = 0; j < 8; j++)
            o[rf][j][0] = o[rf][j][1] = o[rf][j][2] = o[rf][j][3] = 0.f;
    float mr[2][2] = {{-1e30f, -1e30f}, {-1e30f, -1e30f}};
    float ll[2][2] = {{0.f, 0.f}, {0.f, 0.f}};

    const int qrow = qt * 128 + w * 32 + g;
    float* Pw = Qs + (w * 32) * AKL;

    for (int kt = 0; kt < 16; kt++) {
        asm volatile("cp.async.wait_group 0;");
        __syncthreads();
        if (kt + 1 < 16) load_kv(kt + 1);

        const float* Ks = Ksb[kt & 1];
        const float* Vs = Vsb[kt & 1];

        // S = Q K^T (scores in log2 domain via q pre-scale)
        float s[2][8][4];
#pragma unroll
        for (int j = 0; j < 8; j++) {
            s[0][j][0] = s[0][j][1] = s[0][j][2] = s[0][j][3] = 0.f;
            s[1][j][0] = s[1][j][1] = s[1][j][2] = s[1][j][3] = 0.f;
#pragma unroll
            for (int ks = 0; ks < 8; ks++) {
                unsigned b0 = __float_as_uint(Ks[(j * 8 + g) * AKL + ks * 8 + t]);
                unsigned b1 = __float_as_uint(Ks[(j * 8 + g) * AKL + ks * 8 + t + 4]);
                mma8(s[0][j], qa[0][ks], b0, b1);
                mma8(s[1][j], qa[1][ks], b0, b1);
            }
        }

        // mask + online softmax (log2 domain, raw EX2)
        const size_t mbi = ((size_t)b * 16 + kt) * 1024;
#pragma unroll
        for (int rf = 0; rf < 2; rf++) {
            const unsigned long long mb0 = g_maskbits[mbi + qrow + rf * 16];
            const unsigned long long mb1 = g_maskbits[mbi + qrow + rf * 16 + 8];
#pragma unroll
            for (int j = 0; j < 8; j++) {
                int c0 = j * 8 + t * 2;
                s[rf][j][0] = ((mb0 >> c0) & 1ULL) ? s[rf][j][0] : -1e30f;
                s[rf][j][1] = ((mb0 >> (c0 + 1)) & 1ULL) ? s[rf][j][1] : -1e30f;
                s[rf][j][2] = ((mb1 >> c0) & 1ULL) ? s[rf][j][2] : -1e30f;
                s[rf][j][3] = ((mb1 >> (c0 + 1)) & 1ULL) ? s[rf][j][3] : -1e30f;
            }
            float rm0 = -1e30f, rm1 = -1e30f;
#pragma unroll
            for (int j = 0; j < 8; j++) {
                rm0 = fmaxf(rm0, fmaxf(s[rf][j][0], s[rf][j][1]));
                rm1 = fmaxf(rm1, fmaxf(s[rf][j][2], s[rf][j][3]));
            }
            rm0 = fmaxf(rm0, __shfl_xor_sync(0xffffffffu, rm0, 1));
            rm0 = fmaxf(rm0, __shfl_xor_sync(0xffffffffu, rm0, 2));
            rm1 = fmaxf(rm1, __shfl_xor_sync(0xffffffffu, rm1, 1));
            rm1 = fmaxf(rm1, __shfl_xor_sync(0xffffffffu, rm1, 2));
            float mn0 = fmaxf(mr[rf][0], rm0), mn1 = fmaxf(mr[rf][1], rm1);
            float al0 = ex2_fast(mr[rf][0] - mn0), al1 = ex2_fast(mr[rf][1] - mn1);
            float sum0 = 0.f, sum1 = 0.f;
            float* Prf = Pw + rf * 16 * AKL;
#pragma unroll
            for (int j = 0; j < 8; j++) {
                float p0 = ex2_fast(s[rf][j][0] - mn0);
                float p1 = ex2_fast(s[rf][j][1] - mn0);
                float p2 = ex2_fast(s[rf][j][2] - mn1);
                float p3 = ex2_fast(s[rf][j][3] - mn1);
                sum0 += p0 + p1; sum1 += p2 + p3;
                *(float2*)(Prf + g * AKL + j * 8 + t * 2) =
                    make_float2(to_tf32(p0), to_tf32(p1));
                *(float2*)(Prf + (g + 8) * AKL + j * 8 + t * 2) =
                    make_float2(to_tf32(p2), to_tf32(p3));
            }
            sum0 += __shfl_xor_sync(0xffffffffu, sum0, 1);
            sum0 += __shfl_xor_sync(0xffffffffu, sum0, 2);
            sum1 += __shfl_xor_sync(0xffffffffu, sum1, 1);
            sum1 += __shfl_xor_sync(0xffffffffu, sum1, 2);
            ll[rf][0] = ll[rf][0] * al0 + sum0; mr[rf][0] = mn0;
            ll[rf][1] = ll[rf][1] * al1 + sum1; mr[rf][1] = mn1;
#pragma unroll
            for (int j = 0; j < 8; j++) {
                o[rf][j][0] *= al0; o[rf][j][1] *= al0;
                o[rf][j][2] *= al1; o[rf][j][3] *= al1;
            }
        }
        __syncwarp();

        // O += P V
#pragma unroll
        for (int ks = 0; ks < 8; ks++) {
            unsigned pa[2][4];
#pragma unroll
            for (int rf = 0; rf < 2; rf++) {
                const float* Prf = Pw + rf * 16 * AKL;
                pa[rf][0] = __float_as_uint(Prf[g * AKL + ks * 8 + t]);
                pa[rf][1] = __float_as_uint(Prf[(g + 8) * AKL + ks * 8 + t]);
                pa[rf][2] = __float_as_uint(Prf[g * AKL + ks * 8 + t + 4]);
                pa[rf][3] = __float_as_uint(Prf[(g + 8) * AKL + ks * 8 + t + 4]);
            }
#pragma unroll
            for (int j = 0; j < 8; j++) {
                unsigned b0 = __float_as_uint(Vs[(ks * 8 + t) * AVL + j * 8 + g]);
                unsigned b1 = __float_as_uint(Vs[(ks * 8 + t + 4) * AVL + j * 8 + g]);
                mma8(o[0][j], pa[0], b0, b1);
                mma8(o[1][j], pa[1], b0, b1);
            }
        }
        __syncwarp();
    }

#pragma unroll
    for (int rf = 0; rf < 2; rf++) {
        const float inv0 = 1.f / ll[rf][0], inv1 = 1.f / ll[rf][1];
        const int lq0 = qt * 128 + w * 32 + rf * 16 + g;
#pragma unroll
        for (int j = 0; j < 8; j++) {
            *(float2*)(g_attn + ((size_t)lq0 * 8 + b) * 1024 + h * 64 + j * 8 + t * 2) =
                make_float2(to_tf32(o[rf][j][0] * inv0), to_tf32(o[rf][j][1] * inv0));
            *(float2*)(g_attn + ((size_t)(lq0 + 8) * 8 + b) * 1024 + h * 64 + j * 8 + t * 2) =
                make_float2(to_tf32(o[rf][j][2] * inv1), to_tf32(o[rf][j][3] * inv1));
        }
    }
}

// ---------------------------------------------------------------------------
// Final bias add — wmma fallback path only (tc path fuses bias)
// ---------------------------------------------------------------------------
__global__ __launch_bounds__(256) void bias_add_kernel(float* __restrict__ out,
                                                       const float* __restrict__ bo)
{
    if (g_use_tc) return;
    const int m = blockIdx.x;
    const int c = threadIdx.x * 4;
    float4 o = *(float4*)(out + (size_t)m * 1024 + c);
    float4 bb = *(const float4*)(bo + c);
    o.x += bb.x; o.y += bb.y; o.z += bb.z; o.w += bb.w;
    *(float4*)(out + (size_t)m * 1024 + c) = o;
}

// ---------------------------------------------------------------------------
// Launch
// ---------------------------------------------------------------------------
extern "C" void kernel_launch(void* const* d_in, const int* in_sizes, int n_in,
                              void* d_out, int out_size)
{
    const float* hs   = (const float*)d_in[0];
    const float* rpe  = (const float*)d_in[1];
    const void* maskp = d_in[2];
    const float* Wqkv = (const float*)d_in[3];
    const float* bqkv = (const float*)d_in[4];
    const float* Wo   = (const float*)d_in[5];
    const float* bo   = (const float*)d_in[6];
    float* out        = (float*)d_out;

    float *hs_p, *wqkv_p, *wo_p, *qkv_p, *attn_p;
    cudaGetSymbolAddress((void**)&hs_p, g_hs);
    cudaGetSymbolAddress((void**)&wqkv_p, g_wqkv);
    cudaGetSymbolAddress((void**)&wo_p, g_wo);
    cudaGetSymbolAddress((void**)&qkv_p, g_qkv);
    cudaGetSymbolAddress((void**)&attn_p, g_attn);

    probe_tc_kernel<<<1, 32>>>();
    detect_mask_mode_kernel<<<1, 256>>>((const unsigned char*)maskp);
    convert_mask_bits_kernel<<<131072 / 256, 256>>>(maskp);
    tf32_round_kernel<<<(8388608 / 4) / 256, 256>>>(hs_p, hs, 8388608 / 4);
    tf32_round_kernel<<<(3145728 / 4) / 256, 256>>>(wqkv_p, Wqkv, 3145728 / 4);
    tf32_round_kernel<<<(1048576 / 4) / 256, 256>>>(wo_p, Wo, 1048576 / 4);

    const int tc_smem = 2048 + 2 * TCSTAGE;
    const int wm_smem = 2 * (ASTG + BSTG) * (int)sizeof(float);
    cudaFuncSetAttribute(gemm_tc_tf32,
                         cudaFuncAttributeMaxDynamicSharedMemorySize, tc_smem);
    cudaFuncSetAttribute(gemm_wmma_tf32,
                         cudaFuncAttributeMaxDynamicSharedMemorySize, wm_smem);

    // Stage 1: QKV projection (dual path; no bias — rope adds bqkv)
    {
        dim3 grid(3072 / 256, 8192 / 128);
        gemm_tc_tf32<<<grid, 128, tc_smem>>>(hs_p, wqkv_p, nullptr, qkv_p, 8192, 3072, 1024);
        gemm_wmma_tf32<<<grid, 256, wm_smem>>>(hs_p, wqkv_p, qkv_p, 8192, 3072, 1024);
    }

    // Stage 2: RoPE + bqkv + transpose
    rope_bias_transpose_kernel<<<8192, 256>>>(rpe, bqkv);

    // Stage 3: attention (R9 shape: 128 threads, 128-row Q tiles, 2 CTAs/SM)
    {
        cudaFuncSetAttribute(attn_tf32_reg,
                             cudaFuncAttributeMaxDynamicSharedMemorySize, ATT_SMEM);
        dim3 grid(128, 8);
        attn_tf32_reg<<<grid, 128, ATT_SMEM>>>();
    }

    // Stage 4: output projection (tc fuses bo; fallback adds it separately)
    {
        dim3 grid(1024 / 256, 8192 / 128);
        gemm_tc_tf32<<<grid, 128, tc_smem>>>(attn_p, wo_p, bo, out, 8192, 1024, 1024);
        gemm_wmma_tf32<<<grid, 256, wm_smem>>>(attn_p, wo_p, out, 8192, 1024, 1024);
        bias_add_kernel<<<8192, 256>>>(out, bo);
    }
}

// round 16
// speedup vs baseline: 1.2689x; 1.1706x over previous
#include <cuda_runtime.h>
#include <cuda_fp16.h>
#include <mma.h>
#include <cstdint>

using namespace nvcuda;

// ---------------------------------------------------------------------------
// VisionSdpaAttention — v13: tcgen05 tf32 GEMMs + fp16 m16n8k16 attention
//   (R15 with the cp.async group-ordering fix: Q wait is wait_group 0)
//   L=1024, B=8, C=1024, H=16, D=64
// ---------------------------------------------------------------------------

#if defined(__CUDA_ARCH_FEAT_SM103_ALL) || defined(__CUDA_ARCH_FEAT_SM100_ALL)
#define HAS_TCGEN05 1
#else
#define HAS_TCGEN05 0
#endif

__device__ float g_hs[8388608];               // tf32-rounded hidden_states
__device__ float g_wqkv[3145728];             // tf32-rounded Wqkv
__device__ float g_wo[1048576];               // tf32-rounded Wo
__device__ float g_qkv[25165824];             // (L*B, 3C)
__device__ __half g_qh[8388608];              // (B,H,L,D) fp16, scaled 0.125*log2(e)
__device__ __half g_kh[8388608];              // (B,H,L,D) fp16
__device__ __half g_vth[8388608];             // (B,H,D,L) fp16  (V transposed)
__device__ float g_attn[8388608];             // (L*B, C) tf32-rounded
__device__ unsigned long long g_maskbits[131072];  // [B][16 kt][1024 rows]
__device__ int g_mask_mode;
__device__ int g_use_tc;

__device__ __forceinline__ float to_tf32(float x) {
    unsigned int u;
    asm("cvt.rna.tf32.f32 %0, %1;" : "=r"(u) : "f"(x));
    return __uint_as_float(u);
}
__device__ __forceinline__ float ex2_fast(float x) {
    float r;
    asm("ex2.approx.ftz.f32 %0, %1;" : "=f"(r) : "f"(x));
    return r;
}
__device__ __forceinline__ void cp_async16(void* sptr, const void* gptr) {
    unsigned s = (unsigned)__cvta_generic_to_shared(sptr);
    asm volatile("cp.async.cg.shared.global [%0], [%1], 16;" :: "r"(s), "l"(gptr));
}
__device__ __forceinline__ void cp_async16s(uint32_t saddr, const void* gptr) {
    asm volatile("cp.async.cg.shared.global [%0], [%1], 16;" :: "r"(saddr), "l"(gptr));
}
__device__ __forceinline__ void cp_commit() {
    asm volatile("cp.async.commit_group;");
}
// fp16 mma m16n8k16: D(f32) = A(f16 16x16) * B(f16 16x8) + D
__device__ __forceinline__ void mma16(float* c, const unsigned* a, unsigned b0, unsigned b1) {
    asm volatile(
        "mma.sync.aligned.m16n8k16.row.col.f32.f16.f16.f32 "
        "{%0,%1,%2,%3},{%4,%5,%6,%7},{%8,%9},{%0,%1,%2,%3};"
        : "+f"(c[0]), "+f"(c[1]), "+f"(c[2]), "+f"(c[3])
        : "r"(a[0]), "r"(a[1]), "r"(a[2]), "r"(a[3]), "r"(b0), "r"(b1));
}
__device__ __forceinline__ uint32_t smem_u32(const void* p) {
    return (uint32_t)__cvta_generic_to_shared(p);
}

__global__ void probe_tc_kernel() { if (threadIdx.x == 0) g_use_tc = HAS_TCGEN05; }

// ---------------------------------------------------------------------------
// tf32 rounding copy (GEMM operands)
// ---------------------------------------------------------------------------
__global__ __launch_bounds__(256) void tf32_round_kernel(
    float* __restrict__ dst, const float* __restrict__ src, int n4)
{
    int i = blockIdx.x * 256 + threadIdx.x;
    if (i >= n4) return;
    float4 v = *((const float4*)src + i);
    v.x = to_tf32(v.x); v.y = to_tf32(v.y);
    v.z = to_tf32(v.z); v.w = to_tf32(v.w);
    *((float4*)dst + i) = v;
}

// ---------------------------------------------------------------------------
// Mask detection + bitpack -> layout [b][kt][row]
// ---------------------------------------------------------------------------
__global__ void detect_mask_mode_kernel(const unsigned char* __restrict__ m)
{
    __shared__ int s1, s23;
    const int tid = threadIdx.x;
    if (tid == 0) { s1 = 0; s23 = 0; }
    __syncthreads();
    bool o1 = false, o23 = false;
    for (int i = tid * 4; i < 16384; i += 1024) {
        if (m[i + 1] != 0) o1 = true;
        if (m[i + 2] != 0 || m[i + 3] != 0) o23 = true;
    }
    if (o1) atomicOr(&s1, 1);
    if (o23) atomicOr(&s23, 1);
    __syncthreads();
    if (tid == 0) g_mask_mode = s1 ? 0 : (s23 ? 2 : 1);
}

__global__ __launch_bounds__(256) void convert_mask_bits_kernel(const void* __restrict__ mp)
{
    const int idx = blockIdx.x * 256 + threadIdx.x;   // input word: (b*1024+row)*16+kt
    const int mode = g_mask_mode;
    unsigned long long bits = 0ULL;
    const size_t base = (size_t)idx * 64;
    if (mode == 0) {
        const uint4* p = (const uint4*)((const unsigned char*)mp + base);
#pragma unroll
        for (int wrd = 0; wrd < 4; wrd++) {
            uint4 v = p[wrd];
            unsigned ws[4] = {v.x, v.y, v.z, v.w};
#pragma unroll
            for (int q = 0; q < 4; q++)
#pragma unroll
                for (int by = 0; by < 4; by++)
                    if ((ws[q] >> (by * 8)) & 0xffu)
                        bits |= 1ULL << (wrd * 16 + q * 4 + by);
        }
    } else if (mode == 1) {
        const int* p = (const int*)mp + base;
#pragma unroll 8
        for (int j = 0; j < 64; j++)
            if (p[j] != 0) bits |= 1ULL << j;
    } else {
        const float* p = (const float*)mp + base;
#pragma unroll 8
        for (int j = 0; j < 64; j++)
            if (p[j] != 0.0f) bits |= 1ULL << j;
    }
    const int b = idx >> 14;
    const int row = (idx >> 4) & 1023;
    const int kt = idx & 15;
    g_maskbits[((size_t)b * 16 + kt) * 1024 + row] = bits;
}

// ===========================================================================
// tcgen05 helpers + GEMM (verified; bias fused in epilogue)
// ===========================================================================
#if HAS_TCGEN05
__device__ __forceinline__ uint32_t elect_one_pred() {
    uint32_t pred;
    asm volatile(
        "{\n\t.reg .pred p;\n\telect.sync _|p, 0xFFFFFFFF;\n\t"
        "selp.b32 %0, 1, 0, p;\n\t}" : "=r"(pred));
    return pred;
}
static __device__ __forceinline__ uint64_t make_desc_sw128(uint32_t addr) {
    return ((uint64_t)2u << 61) | ((uint64_t)1u << 46) | ((uint64_t)64u << 32)
         | ((uint64_t)1u << 16) | ((uint64_t)(addr >> 4) & 0x3FFFu);
}
__device__ __forceinline__ void tcgen05_mma_tf32_ss(
    uint32_t d_tmem, uint64_t a_desc, uint64_t b_desc, uint32_t idesc, bool enable_d)
{
    uint32_t en = enable_d ? 1u : 0u;
    asm volatile(
        "{\n\t.reg .pred p;\n\t"
        "setp.ne.u32 p, %5, 0;\n\t"
        "tcgen05.mma.cta_group::1.kind::tf32 [%0], %1, %2, %3, {%4, %4, %4, %4}, p;\n\t"
        "}"
        :: "r"(d_tmem), "l"(a_desc), "l"(b_desc), "r"(idesc), "r"(0u), "r"(en)
        : "memory");
}
#define TC_LD_X32(r, addr) \
    asm volatile( \
        "tcgen05.ld.sync.aligned.32x32b.x32.b32 " \
        "{%0, %1, %2, %3, %4, %5, %6, %7, " \
        " %8, %9, %10, %11, %12, %13, %14, %15, " \
        " %16, %17, %18, %19, %20, %21, %22, %23, " \
        " %24, %25, %26, %27, %28, %29, %30, %31}, [%32];" \
        : "=r"((r)[0]),  "=r"((r)[1]),  "=r"((r)[2]),  "=r"((r)[3]), \
          "=r"((r)[4]),  "=r"((r)[5]),  "=r"((r)[6]),  "=r"((r)[7]), \
          "=r"((r)[8]),  "=r"((r)[9]),  "=r"((r)[10]), "=r"((r)[11]), \
          "=r"((r)[12]), "=r"((r)[13]), "=r"((r)[14]), "=r"((r)[15]), \
          "=r"((r)[16]), "=r"((r)[17]), "=r"((r)[18]), "=r"((r)[19]), \
          "=r"((r)[20]), "=r"((r)[21]), "=r"((r)[22]), "=r"((r)[23]), \
          "=r"((r)[24]), "=r"((r)[25]), "=r"((r)[26]), "=r"((r)[27]), \
          "=r"((r)[28]), "=r"((r)[29]), "=r"((r)[30]), "=r"((r)[31]) \
        : "r"(addr))
#define MBAR_WAIT(mbar, parity) do {                                              \
    asm volatile(                                                                 \
        "{\n\t.reg .pred P1;\n\t"                                                 \
        "WAIT_LOOP_%=:\n\t"                                                       \
        "mbarrier.try_wait.parity.acquire.cta.shared::cta.b64 P1, [%0], %1, 0x989680;\n\t" \
        "@P1 bra.uni WAIT_DONE_%=;\n\t"                                           \
        "bra.uni WAIT_LOOP_%=;\n\t"                                               \
        "WAIT_DONE_%=:\n\t}"                                                      \
        :: "r"((uint32_t)(mbar)), "r"((uint32_t)(parity)) : "memory");            \
} while (0)
static constexpr uint32_t TC_IDESC_G =
    (1u << 4) | (2u << 7) | (2u << 10) | ((256u / 8) << 17) | ((128u / 16) << 24);
#endif

#define TCSTAGE 49152
#define TCB_OFF 16384

__global__ __launch_bounds__(128) void gemm_tc_tf32(
    const float* __restrict__ A, const float* __restrict__ B,
    const float* __restrict__ bias, float* __restrict__ C, int M, int N, int K)
{
#if HAS_TCGEN05
    extern __shared__ char smem[];
    const uint32_t sb = smem_u32(smem);
    const uint32_t ctrl = sb;
    const uint32_t data = (sb + 16 + 1023) & ~1023u;

    const int bm = blockIdx.y * 128;
    const int bn = blockIdx.x * 256;
    const int tid = threadIdx.x;
    const int wid = tid >> 5;
    const int lane = tid & 31;

    if (wid == 0) {
        asm volatile("tcgen05.alloc.cta_group::1.sync.aligned.shared::cta.b32 [%0], %1;"
            :: "r"(ctrl), "r"(256u) : "memory");
        asm volatile("tcgen05.relinquish_alloc_permit.cta_group::1.sync.aligned;");
    }
    __syncthreads();
    uint32_t tmem;
    asm volatile("ld.shared.b32 %0, [%1];" : "=r"(tmem) : "r"(ctrl));
    if (tid == 0)
        asm volatile("mbarrier.init.shared.b64 [%0], %1;" :: "r"(ctrl + 8), "r"(1u) : "memory");
    __syncthreads();

    const int nk = K / 32;

    auto load_chunk = [&](int it) {
        const uint32_t st = data + (uint32_t)(it & 1) * TCSTAGE;
        const int k0 = it * 32;
#pragma unroll
        for (int i = 0; i < 8; i++) {
            int e = tid + i * 128;
            int r = e >> 3, c = e & 7;
            uint32_t byte = (uint32_t)(r * 128 + c * 16);
            uint32_t sw = byte ^ ((byte >> 3) & 0x70u);
            cp_async16s(st + sw, A + (size_t)(bm + r) * K + k0 + c * 4);
        }
#pragma unroll
        for (int i = 0; i < 16; i++) {
            int e = tid + i * 128;
            int r = e >> 3, c = e & 7;
            uint32_t byte = (uint32_t)(r * 128 + c * 16);
            uint32_t sw = byte ^ ((byte >> 3) & 0x70u);
            cp_async16s(st + TCB_OFF + sw, B + (size_t)(bn + r) * K + k0 + c * 4);
        }
        cp_commit();
    };

    load_chunk(0);

    for (int it = 0; it < nk; it++) {
        asm volatile("cp.async.wait_group 0;");
        __syncthreads();
        asm volatile("fence.proxy.async.shared::cta;" ::: "memory");
        if (wid == 0) {
            const uint32_t st = data + (uint32_t)(it & 1) * TCSTAGE;
            uint64_t ad = make_desc_sw128(st);
            uint64_t bd = make_desc_sw128(st + TCB_OFF);
            if (elect_one_pred()) {
#pragma unroll
                for (int ks = 0; ks < 4; ks++)
                    tcgen05_mma_tf32_ss(tmem, ad + ks * 2, bd + ks * 2, TC_IDESC_G,
                                        (it != 0) || (ks != 0));
                asm volatile(
                    "tcgen05.commit.cta_group::1.mbarrier::arrive::one.shared::cluster.b64 [%0];"
                    :: "r"(ctrl + 8) : "memory");
            }
        }
        if (it + 1 < nk) load_chunk(it + 1);
        MBAR_WAIT(ctrl + 8, it & 1);
    }

    asm volatile("tcgen05.fence::after_thread_sync;" ::: "memory");

    {
        float* Crow = C + (size_t)(bm + wid * 32 + lane) * N + bn;
#pragma unroll
        for (int bt = 0; bt < 8; bt++) {
            uint32_t r32[32];
            TC_LD_X32(r32, tmem + bt * 32);
            asm volatile("tcgen05.wait::ld.sync.aligned;" ::: "memory");
            if (bias != nullptr) {
#pragma unroll
                for (int q = 0; q < 8; q++) {
                    float4 bb = *(const float4*)(bias + bn + bt * 32 + q * 4);
                    float4 o;
                    o.x = __uint_as_float(r32[q * 4 + 0]) + bb.x;
                    o.y = __uint_as_float(r32[q * 4 + 1]) + bb.y;
                    o.z = __uint_as_float(r32[q * 4 + 2]) + bb.z;
                    o.w = __uint_as_float(r32[q * 4 + 3]) + bb.w;
                    *(float4*)(Crow + bt * 32 + q * 4) = o;
                }
            } else {
#pragma unroll
                for (int q = 0; q < 8; q++) {
                    float4 o;
                    o.x = __uint_as_float(r32[q * 4 + 0]);
                    o.y = __uint_as_float(r32[q * 4 + 1]);
                    o.z = __uint_as_float(r32[q * 4 + 2]);
                    o.w = __uint_as_float(r32[q * 4 + 3]);
                    *(float4*)(Crow + bt * 32 + q * 4) = o;
                }
            }
        }
    }

    __syncthreads();
    if (tid == 0)
        asm volatile("mbarrier.inval.shared.b64 [%0];" :: "r"(ctrl + 8) : "memory");
    __syncthreads();
    if (wid == 0)
        asm volatile("tcgen05.dealloc.cta_group::1.sync.aligned.b32 %0, %1;"
            :: "r"(tmem), "r"(256u));
#else
    (void)A; (void)B; (void)bias; (void)C; (void)M; (void)N; (void)K;
#endif
}

// ===========================================================================
// wmma GEMM fallback (non-'a' cubin only)
// ===========================================================================
#define GLDA 36
#define ASTG (128 * GLDA)
#define BSTG (256 * GLDA)

__global__ __launch_bounds__(256) void gemm_wmma_tf32(
    const float* __restrict__ A, const float* __restrict__ B,
    float* __restrict__ C, int M, int N, int K)
{
    if (g_use_tc) return;

    extern __shared__ float sg[];
    float* Asb[2] = { sg,            sg + ASTG };
    float* Bsb[2] = { sg + 2 * ASTG, sg + 2 * ASTG + BSTG };

    const int bm = blockIdx.y * 128;
    const int bn = blockIdx.x * 256;
    const int tid = threadIdx.x;
    const int wid = tid >> 5;
    const int warpM = wid & 1;
    const int warpN = wid >> 1;

    wmma::fragment<wmma::accumulator, 16, 16, 8, float> acc[4][4];
#pragma unroll
    for (int i = 0; i < 4; i++)
#pragma unroll
        for (int j = 0; j < 4; j++) wmma::fill_fragment(acc[i][j], 0.0f);

    const int nk = K / 32;
    auto load_chunk = [&](int it) {
        const int k0 = it * 32;
        float* As = Asb[it & 1];
        float* Bs = Bsb[it & 1];
#pragma unroll
        for (int i = 0; i < 4; i++) {
            int e = tid + i * 256;
            int r = e >> 3, c = (e & 7) * 4;
            cp_async16(As + r * GLDA + c, A + (size_t)(bm + r) * K + k0 + c);
        }
#pragma unroll
        for (int i = 0; i < 8; i++) {
            int e = tid + i * 256;
            int r = e >> 3, c = (e & 7) * 4;
            cp_async16(Bs + r * GLDA + c, B + (size_t)(bn + r) * K + k0 + c);
        }
        cp_commit();
    };
    load_chunk(0);
    for (int it = 0; it < nk; it++) {
        asm volatile("cp.async.wait_group 0;");
        __syncthreads();
        if (it + 1 < nk) load_chunk(it + 1);
        const float* As = Asb[it & 1];
        const float* Bs = Bsb[it & 1];
#pragma unroll
        for (int ks = 0; ks < 4; ks++) {
            wmma::fragment<wmma::matrix_a, 16, 16, 8, wmma::precision::tf32, wmma::row_major> af[4];
            wmma::fragment<wmma::matrix_b, 16, 16, 8, wmma::precision::tf32, wmma::col_major> bf[4];
#pragma unroll
            for (int i = 0; i < 4; i++)
                wmma::load_matrix_sync(af[i], As + (warpM * 64 + i * 16) * GLDA + ks * 8, GLDA);
#pragma unroll
            for (int j = 0; j < 4; j++)
                wmma::load_matrix_sync(bf[j], Bs + (warpN * 64 + j * 16) * GLDA + ks * 8, GLDA);
#pragma unroll
            for (int i = 0; i < 4; i++)
#pragma unroll
                for (int j = 0; j < 4; j++)
                    wmma::mma_sync(acc[i][j], af[i], bf[j], acc[i][j]);
        }
    }
#pragma unroll
    for (int i = 0; i < 4; i++)
#pragma unroll
        for (int j = 0; j < 4; j++)
            wmma::store_matrix_sync(
                C + (size_t)(bm + warpM * 64 + i * 16) * N + bn + warpN * 64 + j * 16,
                acc[i][j], N, wmma::mem_row_major);
}

// ---------------------------------------------------------------------------
// RoPE + bias + transpose -> fp16 q/k and transposed fp16 V
//   q scaled by 0.125*log2(e); V stored (B,H,D,L)
// ---------------------------------------------------------------------------
__global__ __launch_bounds__(256) void rope_bias_transpose_kernel(
    const float* __restrict__ rpe, const float* __restrict__ bq)
{
    __shared__ float cs[32], sn[32];
    const int m = blockIdx.x;   // l*8 + b
    const int l = m >> 3;
    const int b = m & 7;
    const int tid = threadIdx.x;
    if (tid < 32) {
        float a = rpe[l * 32 + tid];
        cs[tid] = cosf(a);
        sn[tid] = sinf(a);
    }
    __syncthreads();
    const float* src = g_qkv + (size_t)m * 3072;
    for (int r = tid; r < 3072; r += 256) {
        int which = r >> 10;
        int hh = (r >> 6) & 15;
        int d = r & 63;
        float x = src[r] + bq[r];
        float val;
        if (which < 2) {
            float xp = src[r ^ 1] + bq[r ^ 1];
            float c = cs[d & 31];
            float s = sn[d & 31];
            val = x * c + ((d & 1) ? xp : -xp) * s;
        } else {
            val = x;
        }
        const int bh = b * 16 + hh;
        if (which == 0) {
            val *= 0.125f * 1.44269504f;
            g_qh[((size_t)bh * 1024 + l) * 64 + d] = __float2half_rn(val);
        } else if (which == 1) {
            g_kh[((size_t)bh * 1024 + l) * 64 + d] = __float2half_rn(val);
        } else {
            g_vth[((size_t)bh * 64 + d) * 1024 + l] = __float2half_rn(val);
        }
    }
}

// ===========================================================================
// Flash attention, fp16 mma m16n8k16, f32 accum, online softmax (log2, EX2).
// 128 threads (4 warps, 32 rows/warp), 128-row Q tiles, grid (128, 8).
// smem (half): Qs[128][72] (doubles as P) + K[2][64][72] + Vt[2][64][72]
//   = 55296 B
// ===========================================================================
#define AKH 72
#define QSTGH (128 * AKH)
#define KSTGH (64 * AKH)
#define ATT_SMEM ((QSTGH + 4 * KSTGH) * (int)sizeof(__half))   // 55296

__global__ __launch_bounds__(128) void attn_fp16()
{
    extern __shared__ __half smh[];
    __half* Qs = smh;                                    // also P strips
    __half* Ksb[2] = { smh + QSTGH,             smh + QSTGH + KSTGH };
    __half* Vtb[2] = { smh + QSTGH + 2 * KSTGH, smh + QSTGH + 3 * KSTGH };

    const int bh = blockIdx.x;
    const int b = bh >> 4;
    const int h = bh & 15;
    const int qt = blockIdx.y;
    const int tid = threadIdx.x;
    const int w = tid >> 5;
    const int lane = tid & 31;
    const int g = lane >> 2;
    const int t = lane & 3;

    const __half* Kg = g_kh + (size_t)bh * 65536;        // [1024 l][64 d]
    const __half* Vtg = g_vth + (size_t)bh * 65536;      // [64 d][1024 l]

    auto load_kv = [&](int kt) {
        __half* Kd = Ksb[kt & 1];
        __half* Vd = Vtb[kt & 1];
#pragma unroll
        for (int i = 0; i < 4; i++) {
            int e = tid + i * 128;          // 0..511 chunks of 8 halves
            int r = e >> 3, c = e & 7;
            cp_async16(Kd + r * AKH + c * 8, Kg + (size_t)(kt * 64 + r) * 64 + c * 8);
            cp_async16(Vd + r * AKH + c * 8, Vtg + (size_t)r * 1024 + kt * 64 + c * 8);
        }
        cp_commit();
    };
    load_kv(0);

    // Q tile: 128 rows x 64 halves
    {
        const __half* Qg = g_qh + ((size_t)bh * 1024 + qt * 128) * 64;
#pragma unroll
        for (int i = 0; i < 8; i++) {
            int e = tid + i * 128;          // 0..1023 chunks
            int r = e >> 3, c = e & 7;
            cp_async16(Qs + r * AKH + c * 8, Qg + (size_t)r * 64 + c * 8);
        }
        cp_commit();
    }
    // FIX (R15 NaN): groups retire in commit order; wait_group 1 would leave
    // the MOST RECENT group (Q) in flight. Wait for everything before reading Q.
    asm volatile("cp.async.wait_group 0;");
    __syncthreads();

    // Q A-fragments: qa[rf][kc][4]  (kc = 4 chunks of k=16)
    unsigned qa[2][4][4];
#pragma unroll
    for (int rf = 0; rf < 2; rf++) {
        const __half* Qw = Qs + (w * 32 + rf * 16) * AKH;
#pragma unroll
        for (int kc = 0; kc < 4; kc++) {
            qa[rf][kc][0] = *(const unsigned*)(Qw + g * AKH + kc * 16 + 2 * t);
            qa[rf][kc][1] = *(const unsigned*)(Qw + (g + 8) * AKH + kc * 16 + 2 * t);
            qa[rf][kc][2] = *(const unsigned*)(Qw + g * AKH + kc * 16 + 2 * t + 8);
            qa[rf][kc][3] = *(const unsigned*)(Qw + (g + 8) * AKH + kc * 16 + 2 * t + 8);
        }
    }
    __syncthreads();   // Qs becomes P strips

    float o[2][8][4];
#pragma unroll
    for (int rf = 0; rf < 2; rf++)
#pragma unroll
        for (int j = 0; j < 8; j++)
            o[rf][j][0] = o[rf][j][1] = o[rf][j][2] = o[rf][j][3] = 0.f;
    float mr[2][2] = {{-1e30f, -1e30f}, {-1e30f, -1e30f}};
    float ll[2][2] = {{0.f, 0.f}, {0.f, 0.f}};

    const int qrow = qt * 128 + w * 32 + g;
    __half* Pw = Qs + (w * 32) * AKH;

    for (int kt = 0; kt < 16; kt++) {
        asm volatile("cp.async.wait_group 0;");
        __syncthreads();
        if (kt + 1 < 16) load_kv(kt + 1);

        const __half* Ks = Ksb[kt & 1];
        const __half* Vt = Vtb[kt & 1];

        // S = Q K^T  (scores in log2 domain via q pre-scale)
        float s[2][8][4];
#pragma unroll
        for (int j = 0; j < 8; j++) {
            s[0][j][0] = s[0][j][1] = s[0][j][2] = s[0][j][3] = 0.f;
            s[1][j][0] = s[1][j][1] = s[1][j][2] = s[1][j][3] = 0.f;
            const __half* Kj = Ks + (j * 8 + g) * AKH;
#pragma unroll
            for (int kc = 0; kc < 4; kc++) {
                unsigned b0 = *(const unsigned*)(Kj + kc * 16 + 2 * t);
                unsigned b1 = *(const unsigned*)(Kj + kc * 16 + 2 * t + 8);
                mma16(s[0][j], qa[0][kc], b0, b1);
                mma16(s[1][j], qa[1][kc], b0, b1);
            }
        }

        // mask + online softmax (log2 domain, raw EX2)
        const size_t mbi = ((size_t)b * 16 + kt) * 1024;
#pragma unroll
        for (int rf = 0; rf < 2; rf++) {
            const unsigned long long mb0 = g_maskbits[mbi + qrow + rf * 16];
            const unsigned long long mb1 = g_maskbits[mbi + qrow + rf * 16 + 8];
#pragma unroll
            for (int j = 0; j < 8; j++) {
                int c0 = j * 8 + t * 2;
                s[rf][j][0] = ((mb0 >> c0) & 1ULL) ? s[rf][j][0] : -1e30f;
                s[rf][j][1] = ((mb0 >> (c0 + 1)) & 1ULL) ? s[rf][j][1] : -1e30f;
                s[rf][j][2] = ((mb1 >> c0) & 1ULL) ? s[rf][j][2] : -1e30f;
                s[rf][j][3] = ((mb1 >> (c0 + 1)) & 1ULL) ? s[rf][j][3] : -1e30f;
            }
            float rm0 = -1e30f, rm1 = -1e30f;
#pragma unroll
            for (int j = 0; j < 8; j++) {
                rm0 = fmaxf(rm0, fmaxf(s[rf][j][0], s[rf][j][1]));
                rm1 = fmaxf(rm1, fmaxf(s[rf][j][2], s[rf][j][3]));
            }
            rm0 = fmaxf(rm0, __shfl_xor_sync(0xffffffffu, rm0, 1));
            rm0 = fmaxf(rm0, __shfl_xor_sync(0xffffffffu, rm0, 2));
            rm1 = fmaxf(rm1, __shfl_xor_sync(0xffffffffu, rm1, 1));
            rm1 = fmaxf(rm1, __shfl_xor_sync(0xffffffffu, rm1, 2));
            float mn0 = fmaxf(mr[rf][0], rm0), mn1 = fmaxf(mr[rf][1], rm1);
            float al0 = ex2_fast(mr[rf][0] - mn0), al1 = ex2_fast(mr[rf][1] - mn1);
            float sum0 = 0.f, sum1 = 0.f;
            __half* Prf = Pw + rf * 16 * AKH;
#pragma unroll
            for (int j = 0; j < 8; j++) {
                float p0 = ex2_fast(s[rf][j][0] - mn0);
                float p1 = ex2_fast(s[rf][j][1] - mn0);
                float p2 = ex2_fast(s[rf][j][2] - mn1);
                float p3 = ex2_fast(s[rf][j][3] - mn1);
                sum0 += p0 + p1; sum1 += p2 + p3;
                *(__half2*)(Prf + g * AKH + j * 8 + 2 * t) = __floats2half2_rn(p0, p1);
                *(__half2*)(Prf + (g + 8) * AKH + j * 8 + 2 * t) = __floats2half2_rn(p2, p3);
            }
            sum0 += __shfl_xor_sync(0xffffffffu, sum0, 1);
            sum0 += __shfl_xor_sync(0xffffffffu, sum0, 2);
            sum1 += __shfl_xor_sync(0xffffffffu, sum1, 1);
            sum1 += __shfl_xor_sync(0xffffffffu, sum1, 2);
            ll[rf][0] = ll[rf][0] * al0 + sum0; mr[rf][0] = mn0;
            ll[rf][1] = ll[rf][1] * al1 + sum1; mr[rf][1] = mn1;
#pragma unroll
            for (int j = 0; j < 8; j++) {
                o[rf][j][0] *= al0; o[rf][j][1] *= al0;
                o[rf][j][2] *= al1; o[rf][j][3] *= al1;
            }
        }
        __syncwarp();

        // O += P V   (A = P rows, k = kv index; B = Vt[d][kv])
#pragma unroll
        for (int kc = 0; kc < 4; kc++) {
            unsigned pa[2][4];
#pragma unroll
            for (int rf = 0; rf < 2; rf++) {
                const __half* Prf = Pw + rf * 16 * AKH;
                pa[rf][0] = *(const unsigned*)(Prf + g * AKH + kc * 16 + 2 * t);
                pa[rf][1] = *(const unsigned*)(Prf + (g + 8) * AKH + kc * 16 + 2 * t);
                pa[rf][2] = *(const unsigned*)(Prf + g * AKH + kc * 16 + 2 * t + 8);
                pa[rf][3] = *(const unsigned*)(Prf + (g + 8) * AKH + kc * 16 + 2 * t + 8);
            }
#pragma unroll
            for (int j = 0; j < 8; j++) {
                const __half* Vj = Vt + (j * 8 + g) * AKH;
                unsigned b0 = *(const unsigned*)(Vj + kc * 16 + 2 * t);
                unsigned b1 = *(const unsigned*)(Vj + kc * 16 + 2 * t + 8);
                mma16(o[0][j], pa[0], b0, b1);
                mma16(o[1][j], pa[1], b0, b1);
            }
        }
        __syncwarp();
    }

#pragma unroll
    for (int rf = 0; rf < 2; rf++) {
        const float inv0 = 1.f / ll[rf][0], inv1 = 1.f / ll[rf][1];
        const int lq0 = qt * 128 + w * 32 + rf * 16 + g;
#pragma unroll
        for (int j = 0; j < 8; j++) {
            *(float2*)(g_attn + ((size_t)lq0 * 8 + b) * 1024 + h * 64 + j * 8 + t * 2) =
                make_float2(to_tf32(o[rf][j][0] * inv0), to_tf32(o[rf][j][1] * inv0));
            *(float2*)(g_attn + ((size_t)(lq0 + 8) * 8 + b) * 1024 + h * 64 + j * 8 + t * 2) =
                make_float2(to_tf32(o[rf][j][2] * inv1), to_tf32(o[rf][j][3] * inv1));
        }
    }
}

// ---------------------------------------------------------------------------
// Final bias add — wmma fallback path only (tc path fuses bias)
// ---------------------------------------------------------------------------
__global__ __launch_bounds__(256) void bias_add_kernel(float* __restrict__ out,
                                                       const float* __restrict__ bo)
{
    if (g_use_tc) return;
    const int m = blockIdx.x;
    const int c = threadIdx.x * 4;
    float4 o = *(float4*)(out + (size_t)m * 1024 + c);
    float4 bb = *(const float4*)(bo + c);
    o.x += bb.x; o.y += bb.y; o.z += bb.z; o.w += bb.w;
    *(float4*)(out + (size_t)m * 1024 + c) = o;
}

// ---------------------------------------------------------------------------
// Launch
// ---------------------------------------------------------------------------
extern "C" void kernel_launch(void* const* d_in, const int* in_sizes, int n_in,
                              void* d_out, int out_size)
{
    const float* hs   = (const float*)d_in[0];
    const float* rpe  = (const float*)d_in[1];
    const void* maskp = d_in[2];
    const float* Wqkv = (const float*)d_in[3];
    const float* bqkv = (const float*)d_in[4];
    const float* Wo   = (const float*)d_in[5];
    const float* bo   = (const float*)d_in[6];
    float* out        = (float*)d_out;

    float *hs_p, *wqkv_p, *wo_p, *qkv_p, *attn_p;
    cudaGetSymbolAddress((void**)&hs_p, g_hs);
    cudaGetSymbolAddress((void**)&wqkv_p, g_wqkv);
    cudaGetSymbolAddress((void**)&wo_p, g_wo);
    cudaGetSymbolAddress((void**)&qkv_p, g_qkv);
    cudaGetSymbolAddress((void**)&attn_p, g_attn);

    probe_tc_kernel<<<1, 32>>>();
    detect_mask_mode_kernel<<<1, 256>>>((const unsigned char*)maskp);
    convert_mask_bits_kernel<<<131072 / 256, 256>>>(maskp);
    tf32_round_kernel<<<(8388608 / 4) / 256, 256>>>(hs_p, hs, 8388608 / 4);
    tf32_round_kernel<<<(3145728 / 4) / 256, 256>>>(wqkv_p, Wqkv, 3145728 / 4);
    tf32_round_kernel<<<(1048576 / 4) / 256, 256>>>(wo_p, Wo, 1048576 / 4);

    const int tc_smem = 2048 + 2 * TCSTAGE;
    const int wm_smem = 2 * (ASTG + BSTG) * (int)sizeof(float);
    cudaFuncSetAttribute(gemm_tc_tf32,
                         cudaFuncAttributeMaxDynamicSharedMemorySize, tc_smem);
    cudaFuncSetAttribute(gemm_wmma_tf32,
                         cudaFuncAttributeMaxDynamicSharedMemorySize, wm_smem);

    // Stage 1: QKV projection (dual path; no bias — rope adds bqkv)
    {
        dim3 grid(3072 / 256, 8192 / 128);
        gemm_tc_tf32<<<grid, 128, tc_smem>>>(hs_p, wqkv_p, nullptr, qkv_p, 8192, 3072, 1024);
        gemm_wmma_tf32<<<grid, 256, wm_smem>>>(hs_p, wqkv_p, qkv_p, 8192, 3072, 1024);
    }

    // Stage 2: RoPE + bqkv + transpose -> fp16 q/k + transposed fp16 V
    rope_bias_transpose_kernel<<<8192, 256>>>(rpe, bqkv);

    // Stage 3: attention (fp16 m16n8k16, 55KB smem)
    {
        cudaFuncSetAttribute(attn_fp16,
                             cudaFuncAttributeMaxDynamicSharedMemorySize, ATT_SMEM);
        dim3 grid(128, 8);
        attn_fp16<<<grid, 128, ATT_SMEM>>>();
    }

    // Stage 4: output projection (tc fuses bo; fallback adds it separately)
    {
        dim3 grid(1024 / 256, 8192 / 128);
        gemm_tc_tf32<<<grid, 128, tc_smem>>>(attn_p, wo_p, bo, out, 8192, 1024, 1024);
        gemm_wmma_tf32<<<grid, 256, wm_smem>>>(attn_p, wo_p, out, 8192, 1024, 1024);
        bias_add_kernel<<<8192, 256>>>(out, bo);
    }
}

// round 17
// speedup vs baseline: 1.4407x; 1.1354x over previous
#include <cuda_runtime.h>
#include <cuda_fp16.h>
#include <mma.h>
#include <cstdint>

using namespace nvcuda;

// ---------------------------------------------------------------------------
// VisionSdpaAttention — v14: full fp16 datapath
//   tcgen05 kind::f16 GEMMs (bias fused) + fp16 m16n8k16 attention
//   L=1024, B=8, C=1024, H=16, D=64
// ---------------------------------------------------------------------------

#if defined(__CUDA_ARCH_FEAT_SM103_ALL) || defined(__CUDA_ARCH_FEAT_SM100_ALL)
#define HAS_TCGEN05 1
#else
#define HAS_TCGEN05 0
#endif

__device__ __half g_hsh[8388608];             // fp16 hidden_states
__device__ __half g_wqkvh[3145728];           // fp16 Wqkv
__device__ __half g_woh[1048576];             // fp16 Wo
__device__ float g_qkv[25165824];             // (L*B, 3C) f32 (GEMM1 out)
__device__ __half g_qh[8388608];              // (B,H,L,D) fp16, scaled 0.125*log2(e)
__device__ __half g_kh[8388608];              // (B,H,L,D) fp16
__device__ __half g_vth[8388608];             // (B,H,D,L) fp16  (V transposed)
__device__ __half g_attnh[8388608];           // (L*B, C) fp16 (attention out)
__device__ unsigned long long g_maskbits[131072];  // [B][16 kt][1024 rows]
__device__ int g_mask_mode;
__device__ int g_use_tc;

__device__ __forceinline__ float ex2_fast(float x) {
    float r;
    asm("ex2.approx.ftz.f32 %0, %1;" : "=f"(r) : "f"(x));
    return r;
}
__device__ __forceinline__ void cp_async16(void* sptr, const void* gptr) {
    unsigned s = (unsigned)__cvta_generic_to_shared(sptr);
    asm volatile("cp.async.cg.shared.global [%0], [%1], 16;" :: "r"(s), "l"(gptr));
}
__device__ __forceinline__ void cp_async16s(uint32_t saddr, const void* gptr) {
    asm volatile("cp.async.cg.shared.global [%0], [%1], 16;" :: "r"(saddr), "l"(gptr));
}
__device__ __forceinline__ void cp_commit() {
    asm volatile("cp.async.commit_group;");
}
// fp16 mma m16n8k16: D(f32) = A(f16 16x16) * B(f16 16x8) + D
__device__ __forceinline__ void mma16(float* c, const unsigned* a, unsigned b0, unsigned b1) {
    asm volatile(
        "mma.sync.aligned.m16n8k16.row.col.f32.f16.f16.f32 "
        "{%0,%1,%2,%3},{%4,%5,%6,%7},{%8,%9},{%0,%1,%2,%3};"
        : "+f"(c[0]), "+f"(c[1]), "+f"(c[2]), "+f"(c[3])
        : "r"(a[0]), "r"(a[1]), "r"(a[2]), "r"(a[3]), "r"(b0), "r"(b1));
}
__device__ __forceinline__ uint32_t smem_u32(const void* p) {
    return (uint32_t)__cvta_generic_to_shared(p);
}

__global__ void probe_tc_kernel() { if (threadIdx.x == 0) g_use_tc = HAS_TCGEN05; }

// ---------------------------------------------------------------------------
// f32 -> fp16 converter (GEMM operands)
// ---------------------------------------------------------------------------
__global__ __launch_bounds__(256) void f16_convert_kernel(
    __half* __restrict__ dst, const float* __restrict__ src, int n4)
{
    int i = blockIdx.x * 256 + threadIdx.x;
    if (i >= n4) return;
    float4 v = *((const float4*)src + i);
    __half2 lo = __floats2half2_rn(v.x, v.y);
    __half2 hi = __floats2half2_rn(v.z, v.w);
    *((uint2*)dst + i) = make_uint2(*(unsigned*)&lo, *(unsigned*)&hi);
}

// ---------------------------------------------------------------------------
// Mask detection + bitpack -> layout [b][kt][row]
// ---------------------------------------------------------------------------
__global__ void detect_mask_mode_kernel(const unsigned char* __restrict__ m)
{
    __shared__ int s1, s23;
    const int tid = threadIdx.x;
    if (tid == 0) { s1 = 0; s23 = 0; }
    __syncthreads();
    bool o1 = false, o23 = false;
    for (int i = tid * 4; i < 16384; i += 1024) {
        if (m[i + 1] != 0) o1 = true;
        if (m[i + 2] != 0 || m[i + 3] != 0) o23 = true;
    }
    if (o1) atomicOr(&s1, 1);
    if (o23) atomicOr(&s23, 1);
    __syncthreads();
    if (tid == 0) g_mask_mode = s1 ? 0 : (s23 ? 2 : 1);
}

__global__ __launch_bounds__(256) void convert_mask_bits_kernel(const void* __restrict__ mp)
{
    const int idx = blockIdx.x * 256 + threadIdx.x;   // input word: (b*1024+row)*16+kt
    const int mode = g_mask_mode;
    unsigned long long bits = 0ULL;
    const size_t base = (size_t)idx * 64;
    if (mode == 0) {
        const uint4* p = (const uint4*)((const unsigned char*)mp + base);
#pragma unroll
        for (int wrd = 0; wrd < 4; wrd++) {
            uint4 v = p[wrd];
            unsigned ws[4] = {v.x, v.y, v.z, v.w};
#pragma unroll
            for (int q = 0; q < 4; q++)
#pragma unroll
                for (int by = 0; by < 4; by++)
                    if ((ws[q] >> (by * 8)) & 0xffu)
                        bits |= 1ULL << (wrd * 16 + q * 4 + by);
        }
    } else if (mode == 1) {
        const int* p = (const int*)mp + base;
#pragma unroll 8
        for (int j = 0; j < 64; j++)
            if (p[j] != 0) bits |= 1ULL << j;
    } else {
        const float* p = (const float*)mp + base;
#pragma unroll 8
        for (int j = 0; j < 64; j++)
            if (p[j] != 0.0f) bits |= 1ULL << j;
    }
    const int b = idx >> 14;
    const int row = (idx >> 4) & 1023;
    const int kt = idx & 15;
    g_maskbits[((size_t)b * 16 + kt) * 1024 + row] = bits;
}

// ===========================================================================
// tcgen05 helpers + fp16 GEMM (kind::f16; bias fused in epilogue)
// Tile 128x256, BK=64 halves (128B rows = SW128 atom), double-buffered.
// K_per_mma = 16 -> 4 dispatches per chunk, desc offset +2 (32B) per step.
// ===========================================================================
#if HAS_TCGEN05
__device__ __forceinline__ uint32_t elect_one_pred() {
    uint32_t pred;
    asm volatile(
        "{\n\t.reg .pred p;\n\telect.sync _|p, 0xFFFFFFFF;\n\t"
        "selp.b32 %0, 1, 0, p;\n\t}" : "=r"(pred));
    return pred;
}
static __device__ __forceinline__ uint64_t make_desc_sw128(uint32_t addr) {
    return ((uint64_t)2u << 61) | ((uint64_t)1u << 46) | ((uint64_t)64u << 32)
         | ((uint64_t)1u << 16) | ((uint64_t)(addr >> 4) & 0x3FFFu);
}
// kind::f16 SS: atype=btype=F16(0); D=F32(1)<<4; (N/8)<<17; (M/16)<<24
__device__ __forceinline__ void tcgen05_mma_f16_ss(
    uint32_t d_tmem, uint64_t a_desc, uint64_t b_desc, uint32_t idesc, bool enable_d)
{
    uint32_t en = enable_d ? 1u : 0u;
    asm volatile(
        "{\n\t.reg .pred p;\n\t"
        "setp.ne.u32 p, %5, 0;\n\t"
        "tcgen05.mma.cta_group::1.kind::f16 [%0], %1, %2, %3, {%4, %4, %4, %4}, p;\n\t"
        "}"
        :: "r"(d_tmem), "l"(a_desc), "l"(b_desc), "r"(idesc), "r"(0u), "r"(en)
        : "memory");
}
#define TC_LD_X32(r, addr) \
    asm volatile( \
        "tcgen05.ld.sync.aligned.32x32b.x32.b32 " \
        "{%0, %1, %2, %3, %4, %5, %6, %7, " \
        " %8, %9, %10, %11, %12, %13, %14, %15, " \
        " %16, %17, %18, %19, %20, %21, %22, %23, " \
        " %24, %25, %26, %27, %28, %29, %30, %31}, [%32];" \
        : "=r"((r)[0]),  "=r"((r)[1]),  "=r"((r)[2]),  "=r"((r)[3]), \
          "=r"((r)[4]),  "=r"((r)[5]),  "=r"((r)[6]),  "=r"((r)[7]), \
          "=r"((r)[8]),  "=r"((r)[9]),  "=r"((r)[10]), "=r"((r)[11]), \
          "=r"((r)[12]), "=r"((r)[13]), "=r"((r)[14]), "=r"((r)[15]), \
          "=r"((r)[16]), "=r"((r)[17]), "=r"((r)[18]), "=r"((r)[19]), \
          "=r"((r)[20]), "=r"((r)[21]), "=r"((r)[22]), "=r"((r)[23]), \
          "=r"((r)[24]), "=r"((r)[25]), "=r"((r)[26]), "=r"((r)[27]), \
          "=r"((r)[28]), "=r"((r)[29]), "=r"((r)[30]), "=r"((r)[31]) \
        : "r"(addr))
#define MBAR_WAIT(mbar, parity) do {                                              \
    asm volatile(                                                                 \
        "{\n\t.reg .pred P1;\n\t"                                                 \
        "WAIT_LOOP_%=:\n\t"                                                       \
        "mbarrier.try_wait.parity.acquire.cta.shared::cta.b64 P1, [%0], %1, 0x989680;\n\t" \
        "@P1 bra.uni WAIT_DONE_%=;\n\t"                                           \
        "bra.uni WAIT_LOOP_%=;\n\t"                                               \
        "WAIT_DONE_%=:\n\t}"                                                      \
        :: "r"((uint32_t)(mbar)), "r"((uint32_t)(parity)) : "memory");            \
} while (0)
static constexpr uint32_t TC_IDESC_H =
    (1u << 4) | ((256u / 8) << 17) | ((128u / 16) << 24);
#endif

#define TCSTAGE 49152
#define TCB_OFF 16384

__global__ __launch_bounds__(128) void gemm_tc_f16(
    const __half* __restrict__ A, const __half* __restrict__ B,
    const float* __restrict__ bias, float* __restrict__ C, int M, int N, int K)
{
#if HAS_TCGEN05
    extern __shared__ char smem[];
    const uint32_t sb = smem_u32(smem);
    const uint32_t ctrl = sb;
    const uint32_t data = (sb + 16 + 1023) & ~1023u;

    const int bm = blockIdx.y * 128;
    const int bn = blockIdx.x * 256;
    const int tid = threadIdx.x;
    const int wid = tid >> 5;
    const int lane = tid & 31;

    if (wid == 0) {
        asm volatile("tcgen05.alloc.cta_group::1.sync.aligned.shared::cta.b32 [%0], %1;"
            :: "r"(ctrl), "r"(256u) : "memory");
        asm volatile("tcgen05.relinquish_alloc_permit.cta_group::1.sync.aligned;");
    }
    __syncthreads();
    uint32_t tmem;
    asm volatile("ld.shared.b32 %0, [%1];" : "=r"(tmem) : "r"(ctrl));
    if (tid == 0)
        asm volatile("mbarrier.init.shared.b64 [%0], %1;" :: "r"(ctrl + 8), "r"(1u) : "memory");
    __syncthreads();

    const int nk = K / 64;   // 64 halves (128 B) per chunk row

    auto load_chunk = [&](int it) {
        const uint32_t st = data + (uint32_t)(it & 1) * TCSTAGE;
        const int k0 = it * 64;
#pragma unroll
        for (int i = 0; i < 8; i++) {
            int e = tid + i * 128;
            int r = e >> 3, c = e & 7;
            uint32_t byte = (uint32_t)(r * 128 + c * 16);
            uint32_t sw = byte ^ ((byte >> 3) & 0x70u);
            cp_async16s(st + sw, A + (size_t)(bm + r) * K + k0 + c * 8);
        }
#pragma unroll
        for (int i = 0; i < 16; i++) {
            int e = tid + i * 128;
            int r = e >> 3, c = e & 7;
            uint32_t byte = (uint32_t)(r * 128 + c * 16);
            uint32_t sw = byte ^ ((byte >> 3) & 0x70u);
            cp_async16s(st + TCB_OFF + sw, B + (size_t)(bn + r) * K + k0 + c * 8);
        }
        cp_commit();
    };

    load_chunk(0);

    for (int it = 0; it < nk; it++) {
        asm volatile("cp.async.wait_group 0;");
        __syncthreads();
        asm volatile("fence.proxy.async.shared::cta;" ::: "memory");
        if (wid == 0) {
            const uint32_t st = data + (uint32_t)(it & 1) * TCSTAGE;
            uint64_t ad = make_desc_sw128(st);
            uint64_t bd = make_desc_sw128(st + TCB_OFF);
            if (elect_one_pred()) {
#pragma unroll
                for (int ks = 0; ks < 4; ks++)
                    tcgen05_mma_f16_ss(tmem, ad + ks * 2, bd + ks * 2, TC_IDESC_H,
                                       (it != 0) || (ks != 0));
                asm volatile(
                    "tcgen05.commit.cta_group::1.mbarrier::arrive::one.shared::cluster.b64 [%0];"
                    :: "r"(ctrl + 8) : "memory");
            }
        }
        if (it + 1 < nk) load_chunk(it + 1);
        MBAR_WAIT(ctrl + 8, it & 1);
    }

    asm volatile("tcgen05.fence::after_thread_sync;" ::: "memory");

    {
        float* Crow = C + (size_t)(bm + wid * 32 + lane) * N + bn;
#pragma unroll
        for (int bt = 0; bt < 8; bt++) {
            uint32_t r32[32];
            TC_LD_X32(r32, tmem + bt * 32);
            asm volatile("tcgen05.wait::ld.sync.aligned;" ::: "memory");
            if (bias != nullptr) {
#pragma unroll
                for (int q = 0; q < 8; q++) {
                    float4 bb = *(const float4*)(bias + bn + bt * 32 + q * 4);
                    float4 o;
                    o.x = __uint_as_float(r32[q * 4 + 0]) + bb.x;
                    o.y = __uint_as_float(r32[q * 4 + 1]) + bb.y;
                    o.z = __uint_as_float(r32[q * 4 + 2]) + bb.z;
                    o.w = __uint_as_float(r32[q * 4 + 3]) + bb.w;
                    *(float4*)(Crow + bt * 32 + q * 4) = o;
                }
            } else {
#pragma unroll
                for (int q = 0; q < 8; q++) {
                    float4 o;
                    o.x = __uint_as_float(r32[q * 4 + 0]);
                    o.y = __uint_as_float(r32[q * 4 + 1]);
                    o.z = __uint_as_float(r32[q * 4 + 2]);
                    o.w = __uint_as_float(r32[q * 4 + 3]);
                    *(float4*)(Crow + bt * 32 + q * 4) = o;
                }
            }
        }
    }

    __syncthreads();
    if (tid == 0)
        asm volatile("mbarrier.inval.shared.b64 [%0];" :: "r"(ctrl + 8) : "memory");
    __syncthreads();
    if (wid == 0)
        asm volatile("tcgen05.dealloc.cta_group::1.sync.aligned.b32 %0, %1;"
            :: "r"(tmem), "r"(256u));
#else
    (void)A; (void)B; (void)bias; (void)C; (void)M; (void)N; (void)K;
#endif
}

// ===========================================================================
// fp16 wmma GEMM fallback (non-'a' cubin only)
// BM=128, BN=256, BK=32 halves; warp tile 64x64; lda 40 halves (80B, 16B-mult)
// ===========================================================================
#define HLDA 40
#define HASTG (128 * HLDA)
#define HBSTG (256 * HLDA)

__global__ __launch_bounds__(256) void gemm_wmma_f16(
    const __half* __restrict__ A, const __half* __restrict__ B,
    float* __restrict__ C, int M, int N, int K)
{
    if (g_use_tc) return;

    extern __shared__ __half sgh[];
    __half* Asb[2] = { sgh,             sgh + HASTG };
    __half* Bsb[2] = { sgh + 2 * HASTG, sgh + 2 * HASTG + HBSTG };

    const int bm = blockIdx.y * 128;
    const int bn = blockIdx.x * 256;
    const int tid = threadIdx.x;
    const int wid = tid >> 5;
    const int warpM = wid & 1;
    const int warpN = wid >> 1;

    wmma::fragment<wmma::accumulator, 16, 16, 16, float> acc[4][4];
#pragma unroll
    for (int i = 0; i < 4; i++)
#pragma unroll
        for (int j = 0; j < 4; j++) wmma::fill_fragment(acc[i][j], 0.0f);

    const int nk = K / 32;
    auto load_chunk = [&](int it) {
        const int k0 = it * 32;
        __half* As = Asb[it & 1];
        __half* Bs = Bsb[it & 1];
#pragma unroll
        for (int i = 0; i < 2; i++) {            // A: 128 rows x 4 16B chunks
            int e = tid + i * 256;
            int r = e >> 2, c = e & 3;
            cp_async16(As + r * HLDA + c * 8, A + (size_t)(bm + r) * K + k0 + c * 8);
        }
#pragma unroll
        for (int i = 0; i < 4; i++) {            // B: 256 rows x 4
            int e = tid + i * 256;
            int r = e >> 2, c = e & 3;
            cp_async16(Bs + r * HLDA + c * 8, B + (size_t)(bn + r) * K + k0 + c * 8);
        }
        cp_commit();
    };
    load_chunk(0);
    for (int it = 0; it < nk; it++) {
        asm volatile("cp.async.wait_group 0;");
        __syncthreads();
        if (it + 1 < nk) load_chunk(it + 1);
        const __half* As = Asb[it & 1];
        const __half* Bs = Bsb[it & 1];
#pragma unroll
        for (int ks = 0; ks < 2; ks++) {
            wmma::fragment<wmma::matrix_a, 16, 16, 16, half, wmma::row_major> af[4];
            wmma::fragment<wmma::matrix_b, 16, 16, 16, half, wmma::col_major> bf[4];
#pragma unroll
            for (int i = 0; i < 4; i++)
                wmma::load_matrix_sync(af[i], As + (warpM * 64 + i * 16) * HLDA + ks * 16, HLDA);
#pragma unroll
            for (int j = 0; j < 4; j++)
                wmma::load_matrix_sync(bf[j], Bs + (warpN * 64 + j * 16) * HLDA + ks * 16, HLDA);
#pragma unroll
            for (int i = 0; i < 4; i++)
#pragma unroll
                for (int j = 0; j < 4; j++)
                    wmma::mma_sync(acc[i][j], af[i], bf[j], acc[i][j]);
        }
    }
#pragma unroll
    for (int i = 0; i < 4; i++)
#pragma unroll
        for (int j = 0; j < 4; j++)
            wmma::store_matrix_sync(
                C + (size_t)(bm + warpM * 64 + i * 16) * N + bn + warpN * 64 + j * 16,
                acc[i][j], N, wmma::mem_row_major);
}

// ---------------------------------------------------------------------------
// RoPE + bias + transpose -> fp16 q/k and transposed fp16 V
// ---------------------------------------------------------------------------
__global__ __launch_bounds__(256) void rope_bias_transpose_kernel(
    const float* __restrict__ rpe, const float* __restrict__ bq)
{
    __shared__ float cs[32], sn[32];
    const int m = blockIdx.x;   // l*8 + b
    const int l = m >> 3;
    const int b = m & 7;
    const int tid = threadIdx.x;
    if (tid < 32) {
        float a = rpe[l * 32 + tid];
        cs[tid] = cosf(a);
        sn[tid] = sinf(a);
    }
    __syncthreads();
    const float* src = g_qkv + (size_t)m * 3072;
    for (int r = tid; r < 3072; r += 256) {
        int which = r >> 10;
        int hh = (r >> 6) & 15;
        int d = r & 63;
        float x = src[r] + bq[r];
        float val;
        if (which < 2) {
            float xp = src[r ^ 1] + bq[r ^ 1];
            float c = cs[d & 31];
            float s = sn[d & 31];
            val = x * c + ((d & 1) ? xp : -xp) * s;
        } else {
            val = x;
        }
        const int bh = b * 16 + hh;
        if (which == 0) {
            val *= 0.125f * 1.44269504f;
            g_qh[((size_t)bh * 1024 + l) * 64 + d] = __float2half_rn(val);
        } else if (which == 1) {
            g_kh[((size_t)bh * 1024 + l) * 64 + d] = __float2half_rn(val);
        } else {
            g_vth[((size_t)bh * 64 + d) * 1024 + l] = __float2half_rn(val);
        }
    }
}

// ===========================================================================
// Flash attention, fp16 mma m16n8k16 — champion config (R16), fp16 output.
// ===========================================================================
#define AKH 72
#define QSTGH (128 * AKH)
#define KSTGH (64 * AKH)
#define ATT_SMEM ((QSTGH + 4 * KSTGH) * (int)sizeof(__half))   // 55296

__global__ __launch_bounds__(128) void attn_fp16()
{
    extern __shared__ __half smh[];
    __half* Qs = smh;                                    // also P strips
    __half* Ksb[2] = { smh + QSTGH,             smh + QSTGH + KSTGH };
    __half* Vtb[2] = { smh + QSTGH + 2 * KSTGH, smh + QSTGH + 3 * KSTGH };

    const int bh = blockIdx.x;
    const int b = bh >> 4;
    const int h = bh & 15;
    const int qt = blockIdx.y;
    const int tid = threadIdx.x;
    const int w = tid >> 5;
    const int lane = tid & 31;
    const int g = lane >> 2;
    const int t = lane & 3;

    const __half* Kg = g_kh + (size_t)bh * 65536;        // [1024 l][64 d]
    const __half* Vtg = g_vth + (size_t)bh * 65536;      // [64 d][1024 l]

    auto load_kv = [&](int kt) {
        __half* Kd = Ksb[kt & 1];
        __half* Vd = Vtb[kt & 1];
#pragma unroll
        for (int i = 0; i < 4; i++) {
            int e = tid + i * 128;
            int r = e >> 3, c = e & 7;
            cp_async16(Kd + r * AKH + c * 8, Kg + (size_t)(kt * 64 + r) * 64 + c * 8);
            cp_async16(Vd + r * AKH + c * 8, Vtg + (size_t)r * 1024 + kt * 64 + c * 8);
        }
        cp_commit();
    };
    load_kv(0);

    {
        const __half* Qg = g_qh + ((size_t)bh * 1024 + qt * 128) * 64;
#pragma unroll
        for (int i = 0; i < 8; i++) {
            int e = tid + i * 128;
            int r = e >> 3, c = e & 7;
            cp_async16(Qs + r * AKH + c * 8, Qg + (size_t)r * 64 + c * 8);
        }
        cp_commit();
    }
    asm volatile("cp.async.wait_group 0;");   // wait ALL (groups retire in order)
    __syncthreads();

    unsigned qa[2][4][4];
#pragma unroll
    for (int rf = 0; rf < 2; rf++) {
        const __half* Qw = Qs + (w * 32 + rf * 16) * AKH;
#pragma unroll
        for (int kc = 0; kc < 4; kc++) {
            qa[rf][kc][0] = *(const unsigned*)(Qw + g * AKH + kc * 16 + 2 * t);
            qa[rf][kc][1] = *(const unsigned*)(Qw + (g + 8) * AKH + kc * 16 + 2 * t);
            qa[rf][kc][2] = *(const unsigned*)(Qw + g * AKH + kc * 16 + 2 * t + 8);
            qa[rf][kc][3] = *(const unsigned*)(Qw + (g + 8) * AKH + kc * 16 + 2 * t + 8);
        }
    }
    __syncthreads();   // Qs becomes P strips

    float o[2][8][4];
#pragma unroll
    for (int rf = 0; rf < 2; rf++)
#pragma unroll
        for (int j = 0; j < 8; j++)
            o[rf][j][0] = o[rf][j][1] = o[rf][j][2] = o[rf][j][3] = 0.f;
    float mr[2][2] = {{-1e30f, -1e30f}, {-1e30f, -1e30f}};
    float ll[2][2] = {{0.f, 0.f}, {0.f, 0.f}};

    const int qrow = qt * 128 + w * 32 + g;
    __half* Pw = Qs + (w * 32) * AKH;

    for (int kt = 0; kt < 16; kt++) {
        asm volatile("cp.async.wait_group 0;");
        __syncthreads();
        if (kt + 1 < 16) load_kv(kt + 1);

        const __half* Ks = Ksb[kt & 1];
        const __half* Vt = Vtb[kt & 1];

        float s[2][8][4];
#pragma unroll
        for (int j = 0; j < 8; j++) {
            s[0][j][0] = s[0][j][1] = s[0][j][2] = s[0][j][3] = 0.f;
            s[1][j][0] = s[1][j][1] = s[1][j][2] = s[1][j][3] = 0.f;
            const __half* Kj = Ks + (j * 8 + g) * AKH;
#pragma unroll
            for (int kc = 0; kc < 4; kc++) {
                unsigned b0 = *(const unsigned*)(Kj + kc * 16 + 2 * t);
                unsigned b1 = *(const unsigned*)(Kj + kc * 16 + 2 * t + 8);
                mma16(s[0][j], qa[0][kc], b0, b1);
                mma16(s[1][j], qa[1][kc], b0, b1);
            }
        }

        const size_t mbi = ((size_t)b * 16 + kt) * 1024;
#pragma unroll
        for (int rf = 0; rf < 2; rf++) {
            const unsigned long long mb0 = g_maskbits[mbi + qrow + rf * 16];
            const unsigned long long mb1 = g_maskbits[mbi + qrow + rf * 16 + 8];
#pragma unroll
            for (int j = 0; j < 8; j++) {
                int c0 = j * 8 + t * 2;
                s[rf][j][0] = ((mb0 >> c0) & 1ULL) ? s[rf][j][0] : -1e30f;
                s[rf][j][1] = ((mb0 >> (c0 + 1)) & 1ULL) ? s[rf][j][1] : -1e30f;
                s[rf][j][2] = ((mb1 >> c0) & 1ULL) ? s[rf][j][2] : -1e30f;
                s[rf][j][3] = ((mb1 >> (c0 + 1)) & 1ULL) ? s[rf][j][3] : -1e30f;
            }
            float rm0 = -1e30f, rm1 = -1e30f;
#pragma unroll
            for (int j = 0; j < 8; j++) {
                rm0 = fmaxf(rm0, fmaxf(s[rf][j][0], s[rf][j][1]));
                rm1 = fmaxf(rm1, fmaxf(s[rf][j][2], s[rf][j][3]));
            }
            rm0 = fmaxf(rm0, __shfl_xor_sync(0xffffffffu, rm0, 1));
            rm0 = fmaxf(rm0, __shfl_xor_sync(0xffffffffu, rm0, 2));
            rm1 = fmaxf(rm1, __shfl_xor_sync(0xffffffffu, rm1, 1));
            rm1 = fmaxf(rm1, __shfl_xor_sync(0xffffffffu, rm1, 2));
            float mn0 = fmaxf(mr[rf][0], rm0), mn1 = fmaxf(mr[rf][1], rm1);
            float al0 = ex2_fast(mr[rf][0] - mn0), al1 = ex2_fast(mr[rf][1] - mn1);
            float sum0 = 0.f, sum1 = 0.f;
            __half* Prf = Pw + rf * 16 * AKH;
#pragma unroll
            for (int j = 0; j < 8; j++) {
                float p0 = ex2_fast(s[rf][j][0] - mn0);
                float p1 = ex2_fast(s[rf][j][1] - mn0);
                float p2 = ex2_fast(s[rf][j][2] - mn1);
                float p3 = ex2_fast(s[rf][j][3] - mn1);
                sum0 += p0 + p1; sum1 += p2 + p3;
                *(__half2*)(Prf + g * AKH + j * 8 + 2 * t) = __floats2half2_rn(p0, p1);
                *(__half2*)(Prf + (g + 8) * AKH + j * 8 + 2 * t) = __floats2half2_rn(p2, p3);
            }
            sum0 += __shfl_xor_sync(0xffffffffu, sum0, 1);
            sum0 += __shfl_xor_sync(0xffffffffu, sum0, 2);
            sum1 += __shfl_xor_sync(0xffffffffu, sum1, 1);
            sum1 += __shfl_xor_sync(0xffffffffu, sum1, 2);
            ll[rf][0] = ll[rf][0] * al0 + sum0; mr[rf][0] = mn0;
            ll[rf][1] = ll[rf][1] * al1 + sum1; mr[rf][1] = mn1;
#pragma unroll
            for (int j = 0; j < 8; j++) {
                o[rf][j][0] *= al0; o[rf][j][1] *= al0;
                o[rf][j][2] *= al1; o[rf][j][3] *= al1;
            }
        }
        __syncwarp();

#pragma unroll
        for (int kc = 0; kc < 4; kc++) {
            unsigned pa[2][4];
#pragma unroll
            for (int rf = 0; rf < 2; rf++) {
                const __half* Prf = Pw + rf * 16 * AKH;
                pa[rf][0] = *(const unsigned*)(Prf + g * AKH + kc * 16 + 2 * t);
                pa[rf][1] = *(const unsigned*)(Prf + (g + 8) * AKH + kc * 16 + 2 * t);
                pa[rf][2] = *(const unsigned*)(Prf + g * AKH + kc * 16 + 2 * t + 8);
                pa[rf][3] = *(const unsigned*)(Prf + (g + 8) * AKH + kc * 16 + 2 * t + 8);
            }
#pragma unroll
            for (int j = 0; j < 8; j++) {
                const __half* Vj = Vt + (j * 8 + g) * AKH;
                unsigned b0 = *(const unsigned*)(Vj + kc * 16 + 2 * t);
                unsigned b1 = *(const unsigned*)(Vj + kc * 16 + 2 * t + 8);
                mma16(o[0][j], pa[0], b0, b1);
                mma16(o[1][j], pa[1], b0, b1);
            }
        }
        __syncwarp();
    }

    // epilogue: fp16 output for GEMM2
#pragma unroll
    for (int rf = 0; rf < 2; rf++) {
        const float inv0 = 1.f / ll[rf][0], inv1 = 1.f / ll[rf][1];
        const int lq0 = qt * 128 + w * 32 + rf * 16 + g;
#pragma unroll
        for (int j = 0; j < 8; j++) {
            *(__half2*)(g_attnh + ((size_t)lq0 * 8 + b) * 1024 + h * 64 + j * 8 + t * 2) =
                __floats2half2_rn(o[rf][j][0] * inv0, o[rf][j][1] * inv0);
            *(__half2*)(g_attnh + ((size_t)(lq0 + 8) * 8 + b) * 1024 + h * 64 + j * 8 + t * 2) =
                __floats2half2_rn(o[rf][j][2] * inv1, o[rf][j][3] * inv1);
        }
    }
}

// ---------------------------------------------------------------------------
// Final bias add — wmma fallback path only (tc path fuses bias)
// ---------------------------------------------------------------------------
__global__ __launch_bounds__(256) void bias_add_kernel(float* __restrict__ out,
                                                       const float* __restrict__ bo)
{
    if (g_use_tc) return;
    const int m = blockIdx.x;
    const int c = threadIdx.x * 4;
    float4 o = *(float4*)(out + (size_t)m * 1024 + c);
    float4 bb = *(const float4*)(bo + c);
    o.x += bb.x; o.y += bb.y; o.z += bb.z; o.w += bb.w;
    *(float4*)(out + (size_t)m * 1024 + c) = o;
}

// ---------------------------------------------------------------------------
// Launch
// ---------------------------------------------------------------------------
extern "C" void kernel_launch(void* const* d_in, const int* in_sizes, int n_in,
                              void* d_out, int out_size)
{
    const float* hs   = (const float*)d_in[0];
    const float* rpe  = (const float*)d_in[1];
    const void* maskp = d_in[2];
    const float* Wqkv = (const float*)d_in[3];
    const float* bqkv = (const float*)d_in[4];
    const float* Wo   = (const float*)d_in[5];
    const float* bo   = (const float*)d_in[6];
    float* out        = (float*)d_out;

    __half *hsh_p, *wqkvh_p, *woh_p, *attnh_p;
    float *qkv_p;
    cudaGetSymbolAddress((void**)&hsh_p, g_hsh);
    cudaGetSymbolAddress((void**)&wqkvh_p, g_wqkvh);
    cudaGetSymbolAddress((void**)&woh_p, g_woh);
    cudaGetSymbolAddress((void**)&qkv_p, g_qkv);
    cudaGetSymbolAddress((void**)&attnh_p, g_attnh);

    probe_tc_kernel<<<1, 32>>>();
    detect_mask_mode_kernel<<<1, 256>>>((const unsigned char*)maskp);
    convert_mask_bits_kernel<<<131072 / 256, 256>>>(maskp);
    f16_convert_kernel<<<(8388608 / 4) / 256, 256>>>(hsh_p, hs, 8388608 / 4);
    f16_convert_kernel<<<(3145728 / 4) / 256, 256>>>(wqkvh_p, Wqkv, 3145728 / 4);
    f16_convert_kernel<<<(1048576 / 4) / 256, 256>>>(woh_p, Wo, 1048576 / 4);

    const int tc_smem = 2048 + 2 * TCSTAGE;
    const int wm_smem = 2 * (HASTG + HBSTG) * (int)sizeof(__half);
    cudaFuncSetAttribute(gemm_tc_f16,
                         cudaFuncAttributeMaxDynamicSharedMemorySize, tc_smem);
    cudaFuncSetAttribute(gemm_wmma_f16,
                         cudaFuncAttributeMaxDynamicSharedMemorySize, wm_smem);

    // Stage 1: QKV projection (dual path; no bias — rope adds bqkv)
    {
        dim3 grid(3072 / 256, 8192 / 128);
        gemm_tc_f16<<<grid, 128, tc_smem>>>(hsh_p, wqkvh_p, nullptr, qkv_p, 8192, 3072, 1024);
        gemm_wmma_f16<<<grid, 256, wm_smem>>>(hsh_p, wqkvh_p, qkv_p, 8192, 3072, 1024);
    }

    // Stage 2: RoPE + bqkv + transpose -> fp16 q/k + transposed fp16 V
    rope_bias_transpose_kernel<<<8192, 256>>>(rpe, bqkv);

    // Stage 3: attention (fp16 m16n8k16, fp16 output)
    {
        cudaFuncSetAttribute(attn_fp16,
                             cudaFuncAttributeMaxDynamicSharedMemorySize, ATT_SMEM);
        dim3 grid(128, 8);
        attn_fp16<<<grid, 128, ATT_SMEM>>>();
    }

    // Stage 4: output projection (tc fuses bo; fallback adds it separately)
    {
        dim3 grid(1024 / 256, 8192 / 128);
        gemm_tc_f16<<<grid, 128, tc_smem>>>(attnh_p, woh_p, bo, out, 8192, 1024, 1024);
        gemm_wmma_f16<<<grid, 256, wm_smem>>>(attnh_p, woh_p, out, 8192, 1024, 1024);
        bias_add_kernel<<<8192, 256>>>(out, bo);
    }
}